// round 1
// baseline (speedup 1.0000x reference)
#include <cuda_runtime.h>
#include <math.h>

#define HID 64
#define NF 20
#define EF 20
#define NENV 16
#define NNODES 5000
#define NEDGES 50000
#define E2 (2*NEDGES)
#define PAIRS (E2*NENV)          // 1,600,000
#define TILE 64                  // pairs per block
#define NROWS (NENV*NNODES)      // 80,000

// ---- scratch (no allocation allowed) ----
__device__ float g_nf[NENV*NNODES*NF];     // ping-pong node features
__device__ float g_store[NENV*NNODES*EF];  // scatter-add accumulator

// ---- dynamic shared layout (in floats) ----
#define SW1_OFF 0                      // 64 rows x stride 44 (40 used)
#define SW2_OFF (SW1_OFF + 64*44)      // 64 rows x stride 68 (64 used)
#define SW3_OFF (SW2_OFF + 64*68)      // 20 rows x stride 68
#define SB_OFF  (SW3_OFF + 20*68)      // b1[64] b2[64] b3[20] -> 160
#define SX_OFF  (SB_OFF + 160)         // 64 pairs x stride 44 (40 used)
#define SH_OFF  (SX_OFF + 64*44)       // 64 pairs x stride 68 (64 used)
#define SMETA_OFF (SH_OFF + 64*68)     // src[64], dst[64], base[64] as ints
#define SMEM_FLOATS (SMETA_OFF + 192)
#define SMEM_BYTES (SMEM_FLOATS * 4)   // 64,192 B -> 3 CTAs/SM

__global__ void __launch_bounds__(256, 3)
edge_kernel(const float* __restrict__ nf,
            const int*   __restrict__ edges,
            const float* __restrict__ W1, const float* __restrict__ b1,
            const float* __restrict__ W2, const float* __restrict__ b2,
            const float* __restrict__ W3, const float* __restrict__ b3,
            float* __restrict__ store)
{
    extern __shared__ float sm[];
    float* sW1 = sm + SW1_OFF;
    float* sW2 = sm + SW2_OFF;
    float* sW3 = sm + SW3_OFF;
    float* sb1 = sm + SB_OFF;
    float* sb2 = sb1 + 64;
    float* sb3 = sb2 + 64;
    float* sx  = sm + SX_OFF;
    float* sh  = sm + SH_OFF;
    int* ssrc  = (int*)(sm + SMETA_OFF);
    int* sdst  = ssrc + 64;
    int* sbase = sdst + 64;

    const int tid = threadIdx.x;

    // ---- stage weights into SMEM (padded strides) ----
    for (int i = tid; i < 64*40; i += 256) sW1[(i/40)*44 + (i%40)] = W1[i];
    for (int i = tid; i < 64*64; i += 256) sW2[(i>>6)*68 + (i&63)] = W2[i];
    for (int i = tid; i < 20*64; i += 256) sW3[(i>>6)*68 + (i&63)] = W3[i];
    if (tid < 64) { sb1[tid] = b1[tid]; sb2[tid] = b2[tid]; }
    if (tid < 20) { sb3[tid] = b3[tid]; }

    // ---- per-pair metadata: pid = blk*64 + p ; env = pid&15 ; e2 = pid>>4 ----
    if (tid < TILE) {
        int pid = blockIdx.x * TILE + tid;
        int env = pid & 15;
        int e2  = pid >> 4;
        int s = edges[e2];                       // src = e[0][e2] (holds for both halves)
        int d = edges[(e2 + NEDGES) % E2];       // dst
        ssrc[tid]  = env * NNODES + s;
        sdst[tid]  = env * NNODES + d;
        sbase[tid] = (env * NNODES + s) * EF;
    }
    __syncthreads();

    // ---- gather x = [nf[src], nf[dst]] into SMEM ----
    for (int i = tid; i < TILE*40; i += 256) {
        int p = i / 40, k = i % 40;
        float v = (k < 20) ? nf[ssrc[p]*NF + k] : nf[sdst[p]*NF + (k - 20)];
        sx[p*44 + k] = v;
    }
    __syncthreads();

    // thread tile: pg in [0,16) owns pairs pg*4..pg*4+3 ; jg in [0,16) owns j = jg + 16*jj
    const int pg = tid >> 4;
    const int jg = tid & 15;

    float acc[4][4];

    // ================= phase 1: h1 = tanh(x @ W1^T + b1), K=40 =================
    #pragma unroll
    for (int jj = 0; jj < 4; jj++) {
        float b = sb1[jg + 16*jj];
        #pragma unroll
        for (int pi = 0; pi < 4; pi++) acc[pi][jj] = b;
    }
    #pragma unroll
    for (int k4 = 0; k4 < 10; k4++) {
        float4 xv[4], wv[4];
        #pragma unroll
        for (int pi = 0; pi < 4; pi++)
            xv[pi] = *(const float4*)&sx[(pg*4 + pi)*44 + k4*4];
        #pragma unroll
        for (int jj = 0; jj < 4; jj++)
            wv[jj] = *(const float4*)&sW1[(jg + 16*jj)*44 + k4*4];
        #pragma unroll
        for (int pi = 0; pi < 4; pi++)
            #pragma unroll
            for (int jj = 0; jj < 4; jj++) {
                acc[pi][jj] += xv[pi].x*wv[jj].x + xv[pi].y*wv[jj].y
                             + xv[pi].z*wv[jj].z + xv[pi].w*wv[jj].w;
            }
    }
    #pragma unroll
    for (int pi = 0; pi < 4; pi++)
        #pragma unroll
        for (int jj = 0; jj < 4; jj++)
            sh[(pg*4 + pi)*68 + jg + 16*jj] = tanhf(acc[pi][jj]);
    __syncthreads();

    // ================= phase 2: h2 = tanh(h1 @ W2^T + b2), K=64 =================
    #pragma unroll
    for (int jj = 0; jj < 4; jj++) {
        float b = sb2[jg + 16*jj];
        #pragma unroll
        for (int pi = 0; pi < 4; pi++) acc[pi][jj] = b;
    }
    #pragma unroll
    for (int k4 = 0; k4 < 16; k4++) {
        float4 xv[4], wv[4];
        #pragma unroll
        for (int pi = 0; pi < 4; pi++)
            xv[pi] = *(const float4*)&sh[(pg*4 + pi)*68 + k4*4];
        #pragma unroll
        for (int jj = 0; jj < 4; jj++)
            wv[jj] = *(const float4*)&sW2[(jg + 16*jj)*68 + k4*4];
        #pragma unroll
        for (int pi = 0; pi < 4; pi++)
            #pragma unroll
            for (int jj = 0; jj < 4; jj++) {
                acc[pi][jj] += xv[pi].x*wv[jj].x + xv[pi].y*wv[jj].y
                             + xv[pi].z*wv[jj].z + xv[pi].w*wv[jj].w;
            }
    }
    float hh[4][4];
    #pragma unroll
    for (int pi = 0; pi < 4; pi++)
        #pragma unroll
        for (int jj = 0; jj < 4; jj++)
            hh[pi][jj] = tanhf(acc[pi][jj]);
    __syncthreads();   // everyone done READING h1 before overwrite
    #pragma unroll
    for (int pi = 0; pi < 4; pi++)
        #pragma unroll
        for (int jj = 0; jj < 4; jj++)
            sh[(pg*4 + pi)*68 + jg + 16*jj] = hh[pi][jj];
    __syncthreads();

    // ================= phase 3: msg = h2 @ W3^T + b3 (K=64, 20 out), scatter =================
    const int p3 = tid >> 2;       // pair
    const int t3 = tid & 3;        // owns outputs t3*5 .. t3*5+4
    float a3[5];
    #pragma unroll
    for (int j = 0; j < 5; j++) a3[j] = sb3[t3*5 + j];
    #pragma unroll
    for (int k4 = 0; k4 < 16; k4++) {
        float4 hv = *(const float4*)&sh[p3*68 + k4*4];
        #pragma unroll
        for (int j = 0; j < 5; j++) {
            float4 wv = *(const float4*)&sW3[(t3*5 + j)*68 + k4*4];
            a3[j] += hv.x*wv.x + hv.y*wv.y + hv.z*wv.z + hv.w*wv.w;
        }
    }
    int base = sbase[p3];
    #pragma unroll
    for (int j = 0; j < 5; j++)
        atomicAdd(&store[base + t3*5 + j], a3[j]);
}

// ---------------- GRU: one thread per (env,node) row ----------------
__global__ void __launch_bounds__(256)
gru_kernel(const float* __restrict__ nf_in,
           const float* __restrict__ store,
           const float* __restrict__ Wih, const float* __restrict__ Whh,
           const float* __restrict__ bih, const float* __restrict__ bhh,
           float* __restrict__ nf_out)
{
    __shared__ float sWih[60*20], sWhh[60*20], sbih[60], sbhh[60];
    const int tid = threadIdx.x;
    for (int i = tid; i < 1200; i += 256) { sWih[i] = Wih[i]; sWhh[i] = Whh[i]; }
    if (tid < 60) { sbih[tid] = bih[tid]; sbhh[tid] = bhh[tid]; }
    __syncthreads();

    int row = blockIdx.x * 256 + tid;
    if (row >= NROWS) return;

    float m[20], h[20], out[20];
    const float4* mp = (const float4*)(store + row*20);
    const float4* hp = (const float4*)(nf_in + row*20);
    #pragma unroll
    for (int i = 0; i < 5; i++) { ((float4*)m)[i] = mp[i]; ((float4*)h)[i] = hp[i]; }

    #pragma unroll 4
    for (int c = 0; c < 20; c++) {
        float ir = sbih[c],      hr = sbhh[c];
        float iz = sbih[20 + c], hz = sbhh[20 + c];
        float in_ = sbih[40 + c], hn = sbhh[40 + c];
        #pragma unroll
        for (int k = 0; k < 20; k++) {
            ir  += m[k] * sWih[c*20 + k];
            iz  += m[k] * sWih[(20 + c)*20 + k];
            in_ += m[k] * sWih[(40 + c)*20 + k];
            hr  += h[k] * sWhh[c*20 + k];
            hz  += h[k] * sWhh[(20 + c)*20 + k];
            hn  += h[k] * sWhh[(40 + c)*20 + k];
        }
        float r = 1.f / (1.f + expf(-(ir + hr)));
        float z = 1.f / (1.f + expf(-(iz + hz)));
        float n = tanhf(in_ + r * hn);
        out[c] = (1.f - z) * n + z * h[c];
    }
    #pragma unroll
    for (int i = 0; i < 5; i++) ((float4*)(nf_out + row*20))[i] = ((float4*)out)[i];
}

__global__ void zero_kernel(float* __restrict__ p, int n)
{
    int i = blockIdx.x * blockDim.x + threadIdx.x;
    if (i < n) p[i] = 0.f;
}

extern "C" void kernel_launch(void* const* d_in, const int* in_sizes, int n_in,
                              void* d_out, int out_size)
{
    const float* nf0   = (const float*)d_in[0];
    const int*   edges = (const int*)  d_in[1];
    const float* W1 = (const float*)d_in[2];
    const float* b1 = (const float*)d_in[3];
    const float* W2 = (const float*)d_in[4];
    const float* b2 = (const float*)d_in[5];
    const float* W3 = (const float*)d_in[6];
    const float* b3 = (const float*)d_in[7];
    const float* Wih = (const float*)d_in[8];
    const float* Whh = (const float*)d_in[9];
    const float* bih = (const float*)d_in[10];
    const float* bhh = (const float*)d_in[11];
    float* out = (float*)d_out;

    float *nfbuf, *stbuf;
    cudaGetSymbolAddress((void**)&nfbuf, g_nf);
    cudaGetSymbolAddress((void**)&stbuf, g_store);

    cudaFuncSetAttribute(edge_kernel,
                         cudaFuncAttributeMaxDynamicSharedMemorySize, SMEM_BYTES);

    const int nStore = NENV*NNODES*EF;
    for (int it = 0; it < 3; it++) {
        const float* nf_in = (it == 0) ? nf0 : nfbuf;
        float* nf_out = (it == 2) ? out : nfbuf;

        zero_kernel<<<(nStore + 255)/256, 256>>>(stbuf, nStore);
        edge_kernel<<<PAIRS/TILE, 256, SMEM_BYTES>>>(nf_in, edges,
                                                     W1, b1, W2, b2, W3, b3, stbuf);
        gru_kernel<<<(NROWS + 255)/256, 256>>>(nf_in, stbuf, Wih, Whh, bih, bhh, nf_out);
    }
}

// round 3
// speedup vs baseline: 1.5041x; 1.5041x over previous
#include <cuda_runtime.h>
#include <mma.h>
#include <math.h>
#include <stdint.h>

using namespace nvcuda;

#define HID 64
#define NF 20
#define EF 20
#define NENV 16
#define NNODES 5000
#define NEDGES 50000
#define E2 (2*NEDGES)
#define PAIRS (E2*NENV)          // 1,600,000
#define TILE_P 128               // pairs per tile
#define NTILES (PAIRS/TILE_P)    // 12,500
#define NROWS (NENV*NNODES)      // 80,000
#define EDGE_GRID 296

// ---- scratch (no allocation allowed) ----
__device__ float g_nf[NENV*NNODES*NF];     // ping-pong node features
__device__ float g_store[NENV*NNODES*EF];  // scatter-add accumulator

__device__ __forceinline__ float tanh_fast(float x) {
    float y;
    asm("tanh.approx.f32 %0, %1;" : "=f"(y) : "f"(x));
    return y;
}

// ---- shared layout (float offsets) ----
#define STR 68                     // stride for A/H/W2/W3 tiles
#define STR1 44                    // stride for W1 (K=40)
#define OFF_A    0                 // [128][68]  X (cols 0..39) then H2 (cols 0..63)
#define OFF_H    (OFF_A + 128*STR) // [128][68]  H1, then msg (cols 0..31)
#define OFF_W1   (OFF_H + 128*STR) // [64][44]
#define OFF_W2   (OFF_W1 + 64*STR1)// [64][68]
#define OFF_W3   (OFF_W2 + 64*STR) // [32][68]
#define OFF_B1   (OFF_W3 + 32*STR)
#define OFF_B2   (OFF_B1 + 64)
#define OFF_B3   (OFF_B2 + 64)     // 32 (20 used)
#define OFF_BASE (OFF_B3 + 32)     // 128 ints
#define SMEM_FLOATS (OFF_BASE + 128)
#define SMEM_EDGE_BYTES (SMEM_FLOATS * 4)   // 108,288 B -> 2 CTAs/SM

typedef wmma::fragment<wmma::matrix_a, 16, 16, 8, wmma::precision::tf32, wmma::row_major> FragA;
typedef wmma::fragment<wmma::matrix_b, 16, 16, 8, wmma::precision::tf32, wmma::col_major> FragB;
typedef wmma::fragment<wmma::accumulator, 16, 16, 8, float> FragC;

__device__ __forceinline__ void cvt_a(FragA& f) {
    #pragma unroll
    for (int i = 0; i < f.num_elements; i++) f.x[i] = wmma::__float_to_tf32(f.x[i]);
}
__device__ __forceinline__ void cvt_b(FragB& f) {
    #pragma unroll
    for (int i = 0; i < f.num_elements; i++) f.x[i] = wmma::__float_to_tf32(f.x[i]);
}

__global__ void __launch_bounds__(256, 2)
edge_kernel(const float* __restrict__ nf,
            const int*   __restrict__ edges,
            const float* __restrict__ W1, const float* __restrict__ b1,
            const float* __restrict__ W2, const float* __restrict__ b2,
            const float* __restrict__ W3, const float* __restrict__ b3,
            float* __restrict__ store)
{
    extern __shared__ float sm[];
    float* sA  = sm + OFF_A;
    float* sH  = sm + OFF_H;
    float* sW1 = sm + OFF_W1;
    float* sW2 = sm + OFF_W2;
    float* sW3 = sm + OFF_W3;
    float* sb1 = sm + OFF_B1;
    float* sb2 = sm + OFF_B2;
    float* sb3 = sm + OFF_B3;
    int*   sbase = (int*)(sm + OFF_BASE);

    const int tid = threadIdx.x;
    const int wid = tid >> 5;

    // ---- stage weights once per CTA ----
    for (int i = tid; i < 64*40; i += 256) sW1[(i/40)*STR1 + (i%40)] = W1[i];
    for (int i = tid; i < 64*64; i += 256) sW2[(i>>6)*STR + (i&63)] = W2[i];
    for (int i = tid; i < 32*STR; i += 256) sW3[i] = 0.0f;
    if (tid < 64) { sb1[tid] = b1[tid]; sb2[tid] = b2[tid]; }
    if (tid < 32) sb3[tid] = (tid < 20) ? b3[tid] : 0.0f;
    __syncthreads();
    for (int i = tid; i < 20*64; i += 256) sW3[(i>>6)*STR + (i&63)] = W3[i];
    __syncthreads();

    const int r = tid >> 1;        // pair row 0..127
    const int half = tid & 1;

    for (int t = blockIdx.x; t < NTILES; t += gridDim.x) {
        // ========== gather X[128,40]: half 0 -> src (cols 0..19), half 1 -> dst (20..39) ==========
        {
            int pid = t * TILE_P + r;
            int env = pid & 15;
            int e2  = pid >> 4;
            int s = edges[e2];
            int d = edges[(e2 + NEDGES) % E2];
            int row, colbase;
            if (half == 0) {
                row = env * NNODES + s;
                colbase = 0;
                sbase[r] = row * EF;
            } else {
                row = env * NNODES + d;
                colbase = 20;
            }
            const float4* p = (const float4*)(nf + row * NF);
            float4 v0 = p[0], v1 = p[1], v2 = p[2], v3 = p[3], v4 = p[4];
            float* dst = sA + r * STR + colbase;
            *(float4*)(dst +  0) = v0;
            *(float4*)(dst +  4) = v1;
            *(float4*)(dst +  8) = v2;
            *(float4*)(dst + 12) = v3;
            *(float4*)(dst + 16) = v4;
        }
        __syncthreads();

        // ========== phase 1: H1 = X @ W1^T (K=40), warp owns rows [wid*16, wid*16+16) ==========
        {
            FragC acc[4];
            #pragma unroll
            for (int n = 0; n < 4; n++) wmma::fill_fragment(acc[n], 0.0f);
            #pragma unroll
            for (int k = 0; k < 5; k++) {
                FragA a;
                wmma::load_matrix_sync(a, sA + wid*16*STR + k*8, STR);
                cvt_a(a);
                #pragma unroll
                for (int n = 0; n < 4; n++) {
                    FragB b;
                    wmma::load_matrix_sync(b, sW1 + n*16*STR1 + k*8, STR1);
                    cvt_b(b);
                    wmma::mma_sync(acc[n], a, b, acc[n]);
                }
            }
            #pragma unroll
            for (int n = 0; n < 4; n++)
                wmma::store_matrix_sync(sH + wid*16*STR + n*16, acc[n], STR, wmma::mem_row_major);
        }
        __syncthreads();
        // epilogue 1: tanh(H1 + b1) in place
        #pragma unroll
        for (int i = 0; i < 32; i++) {
            int idx = i * 256 + tid;
            int row = idx >> 6, col = idx & 63;
            float* p = sH + row * STR + col;
            *p = tanh_fast(*p + sb1[col]);
        }
        __syncthreads();

        // ========== phase 2: H2 = H1 @ W2^T (K=64) -> sA ==========
        {
            FragC acc[4];
            #pragma unroll
            for (int n = 0; n < 4; n++) wmma::fill_fragment(acc[n], 0.0f);
            #pragma unroll
            for (int k = 0; k < 8; k++) {
                FragA a;
                wmma::load_matrix_sync(a, sH + wid*16*STR + k*8, STR);
                cvt_a(a);
                #pragma unroll
                for (int n = 0; n < 4; n++) {
                    FragB b;
                    wmma::load_matrix_sync(b, sW2 + n*16*STR + k*8, STR);
                    cvt_b(b);
                    wmma::mma_sync(acc[n], a, b, acc[n]);
                }
            }
            #pragma unroll
            for (int n = 0; n < 4; n++)
                wmma::store_matrix_sync(sA + wid*16*STR + n*16, acc[n], STR, wmma::mem_row_major);
        }
        __syncthreads();
        // epilogue 2: tanh(H2 + b2) in place
        #pragma unroll
        for (int i = 0; i < 32; i++) {
            int idx = i * 256 + tid;
            int row = idx >> 6, col = idx & 63;
            float* p = sA + row * STR + col;
            *p = tanh_fast(*p + sb2[col]);
        }
        __syncthreads();

        // ========== phase 3: msg = H2 @ W3^T (K=64, N=32 padded) -> sH ==========
        {
            FragC acc[2];
            wmma::fill_fragment(acc[0], 0.0f);
            wmma::fill_fragment(acc[1], 0.0f);
            #pragma unroll
            for (int k = 0; k < 8; k++) {
                FragA a;
                wmma::load_matrix_sync(a, sA + wid*16*STR + k*8, STR);
                cvt_a(a);
                #pragma unroll
                for (int n = 0; n < 2; n++) {
                    FragB b;
                    wmma::load_matrix_sync(b, sW3 + n*16*STR + k*8, STR);
                    cvt_b(b);
                    wmma::mma_sync(acc[n], a, b, acc[n]);
                }
            }
            wmma::store_matrix_sync(sH + wid*16*STR + 0,  acc[0], STR, wmma::mem_row_major);
            wmma::store_matrix_sync(sH + wid*16*STR + 16, acc[1], STR, wmma::mem_row_major);
        }
        __syncthreads();

        // ========== scatter-add: pair r, half 0 -> cols 0..11, half 1 -> cols 12..19 ==========
        {
            float* dst = store + sbase[r];
            const float* src = sH + r * STR;
            if (half == 0) {
                #pragma unroll
                for (int j = 0; j < 12; j++) atomicAdd(dst + j, src[j] + sb3[j]);
            } else {
                #pragma unroll
                for (int j = 12; j < 20; j++) atomicAdd(dst + j, src[j] + sb3[j]);
            }
        }
        __syncthreads();
    }
}

// ---------------- GRU: one thread per (env,node) row ----------------
__global__ void __launch_bounds__(256)
gru_kernel(const float* __restrict__ nf_in,
           const float* __restrict__ store,
           const float* __restrict__ Wih, const float* __restrict__ Whh,
           const float* __restrict__ bih, const float* __restrict__ bhh,
           float* __restrict__ nf_out)
{
    __shared__ float sWih[60*20], sWhh[60*20], sbih[60], sbhh[60];
    const int tid = threadIdx.x;
    for (int i = tid; i < 1200; i += 256) { sWih[i] = Wih[i]; sWhh[i] = Whh[i]; }
    if (tid < 60) { sbih[tid] = bih[tid]; sbhh[tid] = bhh[tid]; }
    __syncthreads();

    int row = blockIdx.x * 256 + tid;
    if (row >= NROWS) return;

    float m[20], h[20], out[20];
    const float4* mp = (const float4*)(store + row*20);
    const float4* hp = (const float4*)(nf_in + row*20);
    #pragma unroll
    for (int i = 0; i < 5; i++) { ((float4*)m)[i] = mp[i]; ((float4*)h)[i] = hp[i]; }

    #pragma unroll 4
    for (int c = 0; c < 20; c++) {
        float ir = sbih[c],      hr = sbhh[c];
        float iz = sbih[20 + c], hz = sbhh[20 + c];
        float in_ = sbih[40 + c], hn = sbhh[40 + c];
        #pragma unroll
        for (int k = 0; k < 20; k++) {
            ir  += m[k] * sWih[c*20 + k];
            iz  += m[k] * sWih[(20 + c)*20 + k];
            in_ += m[k] * sWih[(40 + c)*20 + k];
            hr  += h[k] * sWhh[c*20 + k];
            hz  += h[k] * sWhh[(20 + c)*20 + k];
            hn  += h[k] * sWhh[(40 + c)*20 + k];
        }
        float rr = 1.f / (1.f + expf(-(ir + hr)));
        float z  = 1.f / (1.f + expf(-(iz + hz)));
        float n  = tanhf(in_ + rr * hn);
        out[c] = (1.f - z) * n + z * h[c];
    }
    #pragma unroll
    for (int i = 0; i < 5; i++) ((float4*)(nf_out + row*20))[i] = ((float4*)out)[i];
}

__global__ void zero_kernel(float* __restrict__ p, int n)
{
    int i = blockIdx.x * blockDim.x + threadIdx.x;
    if (i < n) p[i] = 0.f;
}

extern "C" void kernel_launch(void* const* d_in, const int* in_sizes, int n_in,
                              void* d_out, int out_size)
{
    const float* nf0   = (const float*)d_in[0];
    const int*   edges = (const int*)  d_in[1];
    const float* W1 = (const float*)d_in[2];
    const float* b1 = (const float*)d_in[3];
    const float* W2 = (const float*)d_in[4];
    const float* b2 = (const float*)d_in[5];
    const float* W3 = (const float*)d_in[6];
    const float* b3 = (const float*)d_in[7];
    const float* Wih = (const float*)d_in[8];
    const float* Whh = (const float*)d_in[9];
    const float* bih = (const float*)d_in[10];
    const float* bhh = (const float*)d_in[11];
    float* out = (float*)d_out;

    float *nfbuf, *stbuf;
    cudaGetSymbolAddress((void**)&nfbuf, g_nf);
    cudaGetSymbolAddress((void**)&stbuf, g_store);

    cudaFuncSetAttribute(edge_kernel,
                         cudaFuncAttributeMaxDynamicSharedMemorySize, SMEM_EDGE_BYTES);

    const int nStore = NENV*NNODES*EF;
    for (int it = 0; it < 3; it++) {
        const float* nf_in = (it == 0) ? nf0 : nfbuf;
        float* nf_out = (it == 2) ? out : nfbuf;

        zero_kernel<<<(nStore + 255)/256, 256>>>(stbuf, nStore);
        edge_kernel<<<EDGE_GRID, 256, SMEM_EDGE_BYTES>>>(nf_in, edges,
                                                         W1, b1, W2, b2, W3, b3, stbuf);
        gru_kernel<<<(NROWS + 255)/256, 256>>>(nf_in, stbuf, Wih, Whh, bih, bhh, nf_out);
    }
}

// round 4
// speedup vs baseline: 3.6085x; 2.3991x over previous
#include <cuda_runtime.h>
#include <math.h>
#include <stdint.h>

#define NF 20
#define EF 20
#define NENV 16
#define NNODES 5000
#define NEDGES 50000
#define E2 (2*NEDGES)
#define PAIRS (E2*NENV)          // 1,600,000
#define TILE_P 128
#define NTILES (PAIRS/TILE_P)    // 12,500
#define NROWS (NENV*NNODES)      // 80,000
#define EDGE_GRID 296

// ---- scratch (no allocation allowed) ----
__device__ float g_nf[NROWS*NF];
__device__ float g_store[NROWS*EF];

__device__ __forceinline__ float tanh_fast(float x) {
    float y; asm("tanh.approx.f32 %0, %1;" : "=f"(y) : "f"(x)); return y;
}
__device__ __forceinline__ uint32_t f2tf32(float x) {
    uint32_t r; asm("cvt.rna.tf32.f32 %0, %1;" : "=r"(r) : "f"(x)); return r;
}
__device__ __forceinline__ void mma_tf32(float* d, uint32_t a0, uint32_t a1,
                                         uint32_t a2, uint32_t a3,
                                         uint32_t b0, uint32_t b1) {
    asm volatile("mma.sync.aligned.m16n8k8.row.col.f32.tf32.tf32.f32 "
        "{%0,%1,%2,%3}, {%4,%5,%6,%7}, {%8,%9}, {%0,%1,%2,%3};"
        : "+f"(d[0]), "+f"(d[1]), "+f"(d[2]), "+f"(d[3])
        : "r"(a0), "r"(a1), "r"(a2), "r"(a3), "r"(b0), "r"(b1));
}

// ---- shared layout (32-bit words) ----
#define XSTR 44
#define HSTR 68
#define OFF_W1F 0                       // 40 frags x 64 words
#define OFF_W2F (OFF_W1F + 40*64)       // 64 frags
#define OFF_W3F (OFF_W2F + 64*64)       // 32 frags
#define OFF_X   (OFF_W3F + 32*64)       // 8 warps x 16 x XSTR
#define OFF_H   (OFF_X + 8*16*XSTR)     // 8 warps x 16 x HSTR
#define OFF_BASE (OFF_H + 8*16*HSTR)    // 8 warps x 16 ints
#define OFF_B1  (OFF_BASE + 128)        // 64
#define OFF_B2  (OFF_B1 + 64)           // 64
#define OFF_B3  (OFF_B2 + 64)           // 32 (20 used)
#define SMEM_WORDS (OFF_B3 + 32)
#define SMEM_EDGE_BYTES (SMEM_WORDS * 4)   // 93,312 B -> 2 CTAs/SM

__global__ void __launch_bounds__(256, 2)
edge_kernel(const float* __restrict__ nf,
            const int*   __restrict__ edges,
            const float* __restrict__ W1, const float* __restrict__ b1,
            const float* __restrict__ W2, const float* __restrict__ b2,
            const float* __restrict__ W3, const float* __restrict__ b3,
            float* __restrict__ store)
{
    extern __shared__ uint32_t sm[];
    uint32_t* wf1 = sm + OFF_W1F;
    uint32_t* wf2 = sm + OFF_W2F;
    uint32_t* wf3 = sm + OFF_W3F;
    const int tid  = threadIdx.x;
    const int wid  = tid >> 5;
    const int lane = tid & 31;
    float* sX = (float*)(sm + OFF_X) + wid * 16 * XSTR;
    float* sH = (float*)(sm + OFF_H) + wid * 16 * HSTR;
    int* sbase = (int*)(sm + OFF_BASE) + wid * 16;
    float* sb1 = (float*)(sm + OFF_B1);
    float* sb2 = (float*)(sm + OFF_B2);
    float* sb3 = (float*)(sm + OFF_B3);

    // ---- stage weights in tf32 fragment-major order (once per CTA) ----
    // B frag of m16n8k8.row.col: lane t holds B[n = t/4][k = t%4 + {0,4}] (W is [n][k] row-major)
    for (int s = tid; s < 40*64; s += 256) {
        int f = s >> 6, rem = s & 63, t = rem >> 1, w = rem & 1;
        int kc = f >> 3, ncx = f & 7;
        int n = ncx*8 + (t>>2), k = kc*8 + (t&3) + w*4;
        wf1[s] = f2tf32(W1[n*40 + k]);
    }
    for (int s = tid; s < 64*64; s += 256) {
        int f = s >> 6, rem = s & 63, t = rem >> 1, w = rem & 1;
        int kc = f >> 3, ncx = f & 7;
        int n = ncx*8 + (t>>2), k = kc*8 + (t&3) + w*4;
        wf2[s] = f2tf32(W2[n*64 + k]);
    }
    for (int s = tid; s < 32*64; s += 256) {
        int f = s >> 6, rem = s & 63, t = rem >> 1, w = rem & 1;
        int kc = f >> 2, ncx = f & 3;
        int n = ncx*8 + (t>>2), k = kc*8 + (t&3) + w*4;
        wf3[s] = (n < EF) ? f2tf32(W3[n*64 + k]) : 0u;
    }
    if (tid < 64) { sb1[tid] = b1[tid]; sb2[tid] = b2[tid]; }
    if (tid < 32) sb3[tid] = (tid < EF) ? b3[tid] : 0.0f;
    __syncthreads();

    const int rq = lane >> 2;   // row within m16 (rows rq, rq+8)
    const int cq = lane & 3;    // col quarter

    for (int t = blockIdx.x; t < NTILES; t += gridDim.x) {
        __syncwarp();
        // ---------- gather X[16,40]: 2 lanes per pair ----------
        {
            int r2 = lane >> 1, half = lane & 1;
            int pid = t * TILE_P + wid * 16 + r2;
            int env = pid & 15, e2 = pid >> 4;
            int node = half ? edges[(e2 + NEDGES) % E2] : edges[e2];
            int grow = env * NNODES + node;
            if (!half) sbase[r2] = grow * EF;
            const float4* p = (const float4*)(nf + grow * NF);
            float4 v0 = p[0], v1 = p[1], v2 = p[2], v3 = p[3], v4 = p[4];
            float* dst = sX + r2 * XSTR + half * 20;
            *(float4*)(dst +  0) = v0;
            *(float4*)(dst +  4) = v1;
            *(float4*)(dst +  8) = v2;
            *(float4*)(dst + 12) = v3;
            *(float4*)(dst + 16) = v4;
        }
        __syncwarp();

        // ---------- phase 1: H1 = tanh(X @ W1^T + b1), K=40 ----------
        {
            float acc[8][4];
            #pragma unroll
            for (int n = 0; n < 8; n++)
                acc[n][0] = acc[n][1] = acc[n][2] = acc[n][3] = 0.0f;
            #pragma unroll
            for (int kc = 0; kc < 5; kc++) {
                uint32_t a0 = f2tf32(sX[rq*XSTR + kc*8 + cq]);
                uint32_t a1 = f2tf32(sX[(rq+8)*XSTR + kc*8 + cq]);
                uint32_t a2 = f2tf32(sX[rq*XSTR + kc*8 + cq + 4]);
                uint32_t a3 = f2tf32(sX[(rq+8)*XSTR + kc*8 + cq + 4]);
                #pragma unroll
                for (int n = 0; n < 8; n++) {
                    uint2 b = *(const uint2*)&wf1[(kc*8 + n)*64 + lane*2];
                    mma_tf32(acc[n], a0, a1, a2, a3, b.x, b.y);
                }
            }
            #pragma unroll
            for (int n = 0; n < 8; n++) {
                int c0 = n*8 + 2*cq;
                float bx = sb1[c0], by = sb1[c0+1];
                float2 lo = make_float2(tanh_fast(acc[n][0] + bx), tanh_fast(acc[n][1] + by));
                float2 hi = make_float2(tanh_fast(acc[n][2] + bx), tanh_fast(acc[n][3] + by));
                *(float2*)&sH[rq*HSTR + c0] = lo;
                *(float2*)&sH[(rq+8)*HSTR + c0] = hi;
            }
        }
        __syncwarp();

        // ---------- phase 2: H2 = tanh(H1 @ W2^T + b2), K=64 (in-place) ----------
        {
            float acc[8][4];
            #pragma unroll
            for (int n = 0; n < 8; n++)
                acc[n][0] = acc[n][1] = acc[n][2] = acc[n][3] = 0.0f;
            #pragma unroll
            for (int kc = 0; kc < 8; kc++) {
                uint32_t a0 = f2tf32(sH[rq*HSTR + kc*8 + cq]);
                uint32_t a1 = f2tf32(sH[(rq+8)*HSTR + kc*8 + cq]);
                uint32_t a2 = f2tf32(sH[rq*HSTR + kc*8 + cq + 4]);
                uint32_t a3 = f2tf32(sH[(rq+8)*HSTR + kc*8 + cq + 4]);
                #pragma unroll
                for (int n = 0; n < 8; n++) {
                    uint2 b = *(const uint2*)&wf2[(kc*8 + n)*64 + lane*2];
                    mma_tf32(acc[n], a0, a1, a2, a3, b.x, b.y);
                }
            }
            __syncwarp();   // all lanes finished reading H1 before overwrite
            #pragma unroll
            for (int n = 0; n < 8; n++) {
                int c0 = n*8 + 2*cq;
                float bx = sb2[c0], by = sb2[c0+1];
                float2 lo = make_float2(tanh_fast(acc[n][0] + bx), tanh_fast(acc[n][1] + by));
                float2 hi = make_float2(tanh_fast(acc[n][2] + bx), tanh_fast(acc[n][3] + by));
                *(float2*)&sH[rq*HSTR + c0] = lo;
                *(float2*)&sH[(rq+8)*HSTR + c0] = hi;
            }
        }
        __syncwarp();

        // ---------- phase 3: msg = H2 @ W3^T + b3 (N=32 padded), K=64 ----------
        {
            float acc[4][4];
            #pragma unroll
            for (int n = 0; n < 4; n++)
                acc[n][0] = acc[n][1] = acc[n][2] = acc[n][3] = 0.0f;
            #pragma unroll
            for (int kc = 0; kc < 8; kc++) {
                uint32_t a0 = f2tf32(sH[rq*HSTR + kc*8 + cq]);
                uint32_t a1 = f2tf32(sH[(rq+8)*HSTR + kc*8 + cq]);
                uint32_t a2 = f2tf32(sH[rq*HSTR + kc*8 + cq + 4]);
                uint32_t a3 = f2tf32(sH[(rq+8)*HSTR + kc*8 + cq + 4]);
                #pragma unroll
                for (int n = 0; n < 4; n++) {
                    uint2 b = *(const uint2*)&wf3[(kc*4 + n)*64 + lane*2];
                    mma_tf32(acc[n], a0, a1, a2, a3, b.x, b.y);
                }
            }
            #pragma unroll
            for (int n = 0; n < 4; n++) {      // write msg into sX (cols 0..31 < 44)
                int c0 = n*8 + 2*cq;
                float bx = sb3[c0], by = sb3[c0+1];
                float2 lo = make_float2(acc[n][0] + bx, acc[n][1] + by);
                float2 hi = make_float2(acc[n][2] + bx, acc[n][3] + by);
                *(float2*)&sX[rq*XSTR + c0] = lo;
                *(float2*)&sX[(rq+8)*XSTR + c0] = hi;
            }
        }
        __syncwarp();

        // ---------- scatter-add (vector red): 2 lanes per pair ----------
        {
            int r2 = lane >> 1, half = lane & 1;
            float* dst = store + sbase[r2];
            const float* src = sX + r2 * XSTR;
            if (!half) {
                atomicAdd((float4*)(dst + 0), *(const float4*)(src + 0));
                atomicAdd((float4*)(dst + 4), *(const float4*)(src + 4));
                atomicAdd((float4*)(dst + 8), *(const float4*)(src + 8));
            } else {
                atomicAdd((float4*)(dst + 12), *(const float4*)(src + 12));
                atomicAdd((float4*)(dst + 16), *(const float4*)(src + 16));
            }
        }
    }
}

// ---------------- GRU: one thread per (env,node) row; zeroes store after read ----------------
__global__ void __launch_bounds__(256)
gru_kernel(const float* __restrict__ nf_in,
           float* __restrict__ store,
           const float* __restrict__ Wih, const float* __restrict__ Whh,
           const float* __restrict__ bih, const float* __restrict__ bhh,
           float* __restrict__ nf_out)
{
    __shared__ float sWih[60*20], sWhh[60*20], sbih[60], sbhh[60];
    const int tid = threadIdx.x;
    for (int i = tid; i < 1200; i += 256) { sWih[i] = Wih[i]; sWhh[i] = Whh[i]; }
    if (tid < 60) { sbih[tid] = bih[tid]; sbhh[tid] = bhh[tid]; }
    __syncthreads();

    int row = blockIdx.x * 256 + tid;
    if (row >= NROWS) return;

    float m[20], h[20], out[20];
    float4* mp = (float4*)(store + row*20);
    const float4* hp = (const float4*)(nf_in + row*20);
    #pragma unroll
    for (int i = 0; i < 5; i++) { ((float4*)m)[i] = mp[i]; ((float4*)h)[i] = hp[i]; }
    // restore zeros for next edge pass (keeps store==0 invariant across graph replays)
    float4 z4 = make_float4(0.f, 0.f, 0.f, 0.f);
    #pragma unroll
    for (int i = 0; i < 5; i++) mp[i] = z4;

    #pragma unroll 4
    for (int c = 0; c < 20; c++) {
        float ir = sbih[c],      hr = sbhh[c];
        float iz = sbih[20 + c], hz = sbhh[20 + c];
        float in_ = sbih[40 + c], hn = sbhh[40 + c];
        #pragma unroll
        for (int k = 0; k < 20; k++) {
            ir  += m[k] * sWih[c*20 + k];
            iz  += m[k] * sWih[(20 + c)*20 + k];
            in_ += m[k] * sWih[(40 + c)*20 + k];
            hr  += h[k] * sWhh[c*20 + k];
            hz  += h[k] * sWhh[(20 + c)*20 + k];
            hn  += h[k] * sWhh[(40 + c)*20 + k];
        }
        float rr = 1.f / (1.f + expf(-(ir + hr)));
        float z  = 1.f / (1.f + expf(-(iz + hz)));
        float n  = tanhf(in_ + rr * hn);
        out[c] = (1.f - z) * n + z * h[c];
    }
    #pragma unroll
    for (int i = 0; i < 5; i++) ((float4*)(nf_out + row*20))[i] = ((float4*)out)[i];
}

extern "C" void kernel_launch(void* const* d_in, const int* in_sizes, int n_in,
                              void* d_out, int out_size)
{
    const float* nf0   = (const float*)d_in[0];
    const int*   edges = (const int*)  d_in[1];
    const float* W1 = (const float*)d_in[2];
    const float* b1 = (const float*)d_in[3];
    const float* W2 = (const float*)d_in[4];
    const float* b2 = (const float*)d_in[5];
    const float* W3 = (const float*)d_in[6];
    const float* b3 = (const float*)d_in[7];
    const float* Wih = (const float*)d_in[8];
    const float* Whh = (const float*)d_in[9];
    const float* bih = (const float*)d_in[10];
    const float* bhh = (const float*)d_in[11];
    float* out = (float*)d_out;

    float *nfbuf, *stbuf;
    cudaGetSymbolAddress((void**)&nfbuf, g_nf);
    cudaGetSymbolAddress((void**)&stbuf, g_store);

    cudaFuncSetAttribute(edge_kernel,
                         cudaFuncAttributeMaxDynamicSharedMemorySize, SMEM_EDGE_BYTES);

    for (int it = 0; it < 3; it++) {
        const float* nf_in = (it == 0) ? nf0 : nfbuf;
        float* nf_out = (it == 2) ? out : nfbuf;

        edge_kernel<<<EDGE_GRID, 256, SMEM_EDGE_BYTES>>>(nf_in, edges,
                                                         W1, b1, W2, b2, W3, b3, stbuf);
        gru_kernel<<<(NROWS + 255)/256, 256>>>(nf_in, stbuf, Wih, Whh, bih, bhh, nf_out);
    }
}

// round 5
// speedup vs baseline: 4.1467x; 1.1492x over previous
#include <cuda_runtime.h>
#include <math.h>
#include <stdint.h>

#define NF 20
#define EF 20
#define NENV 16
#define NNODES 5000
#define NEDGES 50000
#define E2 (2*NEDGES)
#define PAIRS (E2*NENV)          // 1,600,000
#define TILE_P 128               // pairs per CTA tile
#define NTILES (PAIRS/TILE_P)    // 12,500
#define NROWS (NENV*NNODES)      // 80,000
#define EDGE_GRID 296

// ---- scratch (no allocation allowed) ----
__device__ float g_nf[NROWS*NF];
__device__ float g_store[NROWS*EF];

__device__ __forceinline__ float tanh_fast(float x) {
    float y; asm("tanh.approx.f32 %0, %1;" : "=f"(y) : "f"(x)); return y;
}
__device__ __forceinline__ uint32_t f2tf32(float x) {
    uint32_t r; asm("cvt.rna.tf32.f32 %0, %1;" : "=r"(r) : "f"(x)); return r;
}
__device__ __forceinline__ void mma_tf32(float* d, uint32_t a0, uint32_t a1,
                                         uint32_t a2, uint32_t a3,
                                         uint32_t b0, uint32_t b1) {
    asm volatile("mma.sync.aligned.m16n8k8.row.col.f32.tf32.tf32.f32 "
        "{%0,%1,%2,%3}, {%4,%5,%6,%7}, {%8,%9}, {%0,%1,%2,%3};"
        : "+f"(d[0]), "+f"(d[1]), "+f"(d[2]), "+f"(d[3])
        : "r"(a0), "r"(a1), "r"(a2), "r"(a3), "r"(b0), "r"(b1));
}

// ---- shared layout (32-bit words) ----
#define XSTR 44
#define HSTR 68
#define OFF_W1F 0                        // 40 frags x 64 words
#define OFF_W2F (OFF_W1F + 40*64)        // 64 frags
#define OFF_W3F (OFF_W2F + 64*64)        // 32 frags
#define OFF_X   (OFF_W3F + 32*64)        // 128 x XSTR (tf32 words / msg floats)
#define OFF_H   (OFF_X + 128*XSTR)       // 128 x HSTR (tf32 words)
#define OFF_BASE (OFF_H + 128*HSTR)      // 128 ints
#define OFF_B1  (OFF_BASE + 128)         // 64
#define OFF_B2  (OFF_B1 + 64)            // 64
#define OFF_B3  (OFF_B2 + 64)            // 32 (20 used)
#define SMEM_WORDS (OFF_B3 + 32)
#define SMEM_EDGE_BYTES (SMEM_WORDS * 4) // 93,312 B -> 2 CTAs/SM

__global__ void __launch_bounds__(128, 2)
edge_kernel(const float* __restrict__ nf,
            const int*   __restrict__ edges,
            const float* __restrict__ W1, const float* __restrict__ b1,
            const float* __restrict__ W2, const float* __restrict__ b2,
            const float* __restrict__ W3, const float* __restrict__ b3,
            float* __restrict__ store)
{
    extern __shared__ uint32_t sm[];
    uint32_t* wf1 = sm + OFF_W1F;
    uint32_t* wf2 = sm + OFF_W2F;
    uint32_t* wf3 = sm + OFF_W3F;
    const int tid  = threadIdx.x;
    const int wid  = tid >> 5;
    const int lane = tid & 31;
    uint32_t* sX = sm + OFF_X + wid * 32 * XSTR;   // this warp's 32 pair rows
    uint32_t* sH = sm + OFF_H + wid * 32 * HSTR;
    int* sbase = (int*)(sm + OFF_BASE) + wid * 32;
    float* sb1 = (float*)(sm + OFF_B1);
    float* sb2 = (float*)(sm + OFF_B2);
    float* sb3 = (float*)(sm + OFF_B3);

    // ---- stage weights in tf32 fragment-major order (once per CTA) ----
    // B frag m16n8k8.row.col: lane t holds B[n=t/4][k=t%4+{0,4}], W row-major [n][k]
    for (int s = tid; s < 40*64; s += 128) {
        int f = s >> 6, rem = s & 63, t = rem >> 1, w = rem & 1;
        int kc = f >> 3, ncx = f & 7;
        int n = ncx*8 + (t>>2), k = kc*8 + (t&3) + w*4;
        wf1[s] = f2tf32(W1[n*40 + k]);
    }
    for (int s = tid; s < 64*64; s += 128) {
        int f = s >> 6, rem = s & 63, t = rem >> 1, w = rem & 1;
        int kc = f >> 3, ncx = f & 7;
        int n = ncx*8 + (t>>2), k = kc*8 + (t&3) + w*4;
        wf2[s] = f2tf32(W2[n*64 + k]);
    }
    for (int s = tid; s < 32*64; s += 128) {
        int f = s >> 6, rem = s & 63, t = rem >> 1, w = rem & 1;
        int kc = f >> 2, ncx = f & 3;
        int n = ncx*8 + (t>>2), k = kc*8 + (t&3) + w*4;
        wf3[s] = (n < EF) ? f2tf32(W3[n*64 + k]) : 0u;
    }
    if (tid < 64) { sb1[tid] = b1[tid]; sb2[tid] = b2[tid]; }
    if (tid < 32) sb3[tid] = (tid < EF) ? b3[tid] : 0.0f;
    __syncthreads();

    const int rq = lane >> 2;   // row in m16 (rows rq, rq+8)
    const int cq = lane & 3;

    for (int t = blockIdx.x; t < NTILES; t += gridDim.x) {
        __syncwarp();
        // ---------- gather: lane p loads pair p's src+dst rows, tf32-convert, store ----------
        {
            int pid = t * TILE_P + wid * 32 + lane;
            int env = pid & 15, e2 = pid >> 4;
            int s = edges[e2];
            int d = edges[(e2 + NEDGES) % E2];
            int srow = env * NNODES + s;
            int drow = env * NNODES + d;
            sbase[lane] = srow * EF;
            const float4* sp = (const float4*)(nf + srow * NF);
            const float4* dp = (const float4*)(nf + drow * NF);
            uint32_t* dst = sX + lane * XSTR;
            #pragma unroll
            for (int j = 0; j < 5; j++) {
                float4 v = sp[j];
                uint4 u = make_uint4(f2tf32(v.x), f2tf32(v.y), f2tf32(v.z), f2tf32(v.w));
                *(uint4*)(dst + j*4) = u;
            }
            #pragma unroll
            for (int j = 0; j < 5; j++) {
                float4 v = dp[j];
                uint4 u = make_uint4(f2tf32(v.x), f2tf32(v.y), f2tf32(v.z), f2tf32(v.w));
                *(uint4*)(dst + 20 + j*4) = u;
            }
        }
        __syncwarp();

        // ---------- phase 1: H1 = tanh(X @ W1^T + b1), K=40, M=32 ----------
        {
            float acc[8][2][4];
            #pragma unroll
            for (int n = 0; n < 8; n++)
                #pragma unroll
                for (int m = 0; m < 2; m++)
                    acc[n][m][0] = acc[n][m][1] = acc[n][m][2] = acc[n][m][3] = 0.0f;
            #pragma unroll
            for (int kc = 0; kc < 5; kc++) {
                uint32_t a[2][4];
                #pragma unroll
                for (int m = 0; m < 2; m++) {
                    int r0 = rq + m*16;
                    a[m][0] = sX[r0*XSTR + kc*8 + cq];
                    a[m][1] = sX[(r0+8)*XSTR + kc*8 + cq];
                    a[m][2] = sX[r0*XSTR + kc*8 + cq + 4];
                    a[m][3] = sX[(r0+8)*XSTR + kc*8 + cq + 4];
                }
                #pragma unroll
                for (int n = 0; n < 8; n++) {
                    uint2 b = *(const uint2*)&wf1[(kc*8 + n)*64 + lane*2];
                    mma_tf32(acc[n][0], a[0][0], a[0][1], a[0][2], a[0][3], b.x, b.y);
                    mma_tf32(acc[n][1], a[1][0], a[1][1], a[1][2], a[1][3], b.x, b.y);
                }
            }
            #pragma unroll
            for (int n = 0; n < 8; n++) {
                int c0 = n*8 + 2*cq;
                float bx = sb1[c0], by = sb1[c0+1];
                #pragma unroll
                for (int m = 0; m < 2; m++) {
                    int r0 = rq + m*16;
                    uint2 lo = make_uint2(f2tf32(tanh_fast(acc[n][m][0] + bx)),
                                          f2tf32(tanh_fast(acc[n][m][1] + by)));
                    uint2 hi = make_uint2(f2tf32(tanh_fast(acc[n][m][2] + bx)),
                                          f2tf32(tanh_fast(acc[n][m][3] + by)));
                    *(uint2*)&sH[r0*HSTR + c0] = lo;
                    *(uint2*)&sH[(r0+8)*HSTR + c0] = hi;
                }
            }
        }
        __syncwarp();

        // ---------- phase 2: H2 = tanh(H1 @ W2^T + b2), K=64, in place ----------
        {
            float acc[8][2][4];
            #pragma unroll
            for (int n = 0; n < 8; n++)
                #pragma unroll
                for (int m = 0; m < 2; m++)
                    acc[n][m][0] = acc[n][m][1] = acc[n][m][2] = acc[n][m][3] = 0.0f;
            #pragma unroll
            for (int kc = 0; kc < 8; kc++) {
                uint32_t a[2][4];
                #pragma unroll
                for (int m = 0; m < 2; m++) {
                    int r0 = rq + m*16;
                    a[m][0] = sH[r0*HSTR + kc*8 + cq];
                    a[m][1] = sH[(r0+8)*HSTR + kc*8 + cq];
                    a[m][2] = sH[r0*HSTR + kc*8 + cq + 4];
                    a[m][3] = sH[(r0+8)*HSTR + kc*8 + cq + 4];
                }
                #pragma unroll
                for (int n = 0; n < 8; n++) {
                    uint2 b = *(const uint2*)&wf2[(kc*8 + n)*64 + lane*2];
                    mma_tf32(acc[n][0], a[0][0], a[0][1], a[0][2], a[0][3], b.x, b.y);
                    mma_tf32(acc[n][1], a[1][0], a[1][1], a[1][2], a[1][3], b.x, b.y);
                }
            }
            __syncwarp();   // all lanes done reading H1 before overwrite
            #pragma unroll
            for (int n = 0; n < 8; n++) {
                int c0 = n*8 + 2*cq;
                float bx = sb2[c0], by = sb2[c0+1];
                #pragma unroll
                for (int m = 0; m < 2; m++) {
                    int r0 = rq + m*16;
                    uint2 lo = make_uint2(f2tf32(tanh_fast(acc[n][m][0] + bx)),
                                          f2tf32(tanh_fast(acc[n][m][1] + by)));
                    uint2 hi = make_uint2(f2tf32(tanh_fast(acc[n][m][2] + bx)),
                                          f2tf32(tanh_fast(acc[n][m][3] + by)));
                    *(uint2*)&sH[r0*HSTR + c0] = lo;
                    *(uint2*)&sH[(r0+8)*HSTR + c0] = hi;
                }
            }
        }
        __syncwarp();

        // ---------- phase 3: msg = H2 @ W3^T + b3 (N=32 padded), K=64 ----------
        {
            float acc[4][2][4];
            #pragma unroll
            for (int n = 0; n < 4; n++)
                #pragma unroll
                for (int m = 0; m < 2; m++)
                    acc[n][m][0] = acc[n][m][1] = acc[n][m][2] = acc[n][m][3] = 0.0f;
            #pragma unroll
            for (int kc = 0; kc < 8; kc++) {
                uint32_t a[2][4];
                #pragma unroll
                for (int m = 0; m < 2; m++) {
                    int r0 = rq + m*16;
                    a[m][0] = sH[r0*HSTR + kc*8 + cq];
                    a[m][1] = sH[(r0+8)*HSTR + kc*8 + cq];
                    a[m][2] = sH[r0*HSTR + kc*8 + cq + 4];
                    a[m][3] = sH[(r0+8)*HSTR + kc*8 + cq + 4];
                }
                #pragma unroll
                for (int n = 0; n < 4; n++) {
                    uint2 b = *(const uint2*)&wf3[(kc*4 + n)*64 + lane*2];
                    mma_tf32(acc[n][0], a[0][0], a[0][1], a[0][2], a[0][3], b.x, b.y);
                    mma_tf32(acc[n][1], a[1][0], a[1][1], a[1][2], a[1][3], b.x, b.y);
                }
            }
            #pragma unroll
            for (int n = 0; n < 4; n++) {      // msg (floats) into sX cols 0..31
                int c0 = n*8 + 2*cq;
                float bx = sb3[c0], by = sb3[c0+1];
                #pragma unroll
                for (int m = 0; m < 2; m++) {
                    int r0 = rq + m*16;
                    float2 lo = make_float2(acc[n][m][0] + bx, acc[n][m][1] + by);
                    float2 hi = make_float2(acc[n][m][2] + bx, acc[n][m][3] + by);
                    *(float2*)&sX[r0*XSTR + c0] = lo;
                    *(float2*)&sX[(r0+8)*XSTR + c0] = hi;
                }
            }
        }
        __syncwarp();

        // ---------- scatter-add: lane p scatters pair p (5 x red.f32x4) ----------
        {
            float* dst = store + sbase[lane];
            const float* src = (const float*)(sX + lane * XSTR);
            atomicAdd((float4*)(dst +  0), *(const float4*)(src +  0));
            atomicAdd((float4*)(dst +  4), *(const float4*)(src +  4));
            atomicAdd((float4*)(dst +  8), *(const float4*)(src +  8));
            atomicAdd((float4*)(dst + 12), *(const float4*)(src + 12));
            atomicAdd((float4*)(dst + 16), *(const float4*)(src + 16));
        }
    }
}

// ---------------- GRU: one thread per (env,node) row; zeroes store after read ----------------
__global__ void __launch_bounds__(256)
gru_kernel(const float* __restrict__ nf_in,
           float* __restrict__ store,
           const float* __restrict__ Wih, const float* __restrict__ Whh,
           const float* __restrict__ bih, const float* __restrict__ bhh,
           float* __restrict__ nf_out)
{
    __shared__ float sWih[60*20], sWhh[60*20], sbih[60], sbhh[60];
    const int tid = threadIdx.x;
    for (int i = tid; i < 1200; i += 256) { sWih[i] = Wih[i]; sWhh[i] = Whh[i]; }
    if (tid < 60) { sbih[tid] = bih[tid]; sbhh[tid] = bhh[tid]; }
    __syncthreads();

    int row = blockIdx.x * 256 + tid;
    if (row >= NROWS) return;

    float m[20], h[20], out[20];
    float4* mp = (float4*)(store + row*20);
    const float4* hp = (const float4*)(nf_in + row*20);
    #pragma unroll
    for (int i = 0; i < 5; i++) { ((float4*)m)[i] = mp[i]; ((float4*)h)[i] = hp[i]; }
    // restore zeros for next edge pass (keeps store==0 invariant across graph replays)
    float4 z4 = make_float4(0.f, 0.f, 0.f, 0.f);
    #pragma unroll
    for (int i = 0; i < 5; i++) mp[i] = z4;

    #pragma unroll 4
    for (int c = 0; c < 20; c++) {
        float ir = sbih[c],      hr = sbhh[c];
        float iz = sbih[20 + c], hz = sbhh[20 + c];
        float in_ = sbih[40 + c], hn = sbhh[40 + c];
        #pragma unroll
        for (int k = 0; k < 20; k++) {
            ir  += m[k] * sWih[c*20 + k];
            iz  += m[k] * sWih[(20 + c)*20 + k];
            in_ += m[k] * sWih[(40 + c)*20 + k];
            hr  += h[k] * sWhh[c*20 + k];
            hz  += h[k] * sWhh[(20 + c)*20 + k];
            hn  += h[k] * sWhh[(40 + c)*20 + k];
        }
        float rr = 1.f / (1.f + expf(-(ir + hr)));
        float z  = 1.f / (1.f + expf(-(iz + hz)));
        float n  = tanhf(in_ + rr * hn);
        out[c] = (1.f - z) * n + z * h[c];
    }
    #pragma unroll
    for (int i = 0; i < 5; i++) ((float4*)(nf_out + row*20))[i] = ((float4*)out)[i];
}

extern "C" void kernel_launch(void* const* d_in, const int* in_sizes, int n_in,
                              void* d_out, int out_size)
{
    const float* nf0   = (const float*)d_in[0];
    const int*   edges = (const int*)  d_in[1];
    const float* W1 = (const float*)d_in[2];
    const float* b1 = (const float*)d_in[3];
    const float* W2 = (const float*)d_in[4];
    const float* b2 = (const float*)d_in[5];
    const float* W3 = (const float*)d_in[6];
    const float* b3 = (const float*)d_in[7];
    const float* Wih = (const float*)d_in[8];
    const float* Whh = (const float*)d_in[9];
    const float* bih = (const float*)d_in[10];
    const float* bhh = (const float*)d_in[11];
    float* out = (float*)d_out;

    float *nfbuf, *stbuf;
    cudaGetSymbolAddress((void**)&nfbuf, g_nf);
    cudaGetSymbolAddress((void**)&stbuf, g_store);

    cudaFuncSetAttribute(edge_kernel,
                         cudaFuncAttributeMaxDynamicSharedMemorySize, SMEM_EDGE_BYTES);

    for (int it = 0; it < 3; it++) {
        const float* nf_in = (it == 0) ? nf0 : nfbuf;
        float* nf_out = (it == 2) ? out : nfbuf;

        edge_kernel<<<EDGE_GRID, 128, SMEM_EDGE_BYTES>>>(nf_in, edges,
                                                         W1, b1, W2, b2, W3, b3, stbuf);
        gru_kernel<<<(NROWS + 255)/256, 256>>>(nf_in, stbuf, Wih, Whh, bih, bhh, nf_out);
    }
}

// round 8
// speedup vs baseline: 5.5609x; 1.3411x over previous
#include <cuda_runtime.h>
#include <cuda_fp16.h>
#include <math.h>
#include <stdint.h>

#define NF 20
#define EF 20
#define NENV 16
#define NNODES 5000
#define NEDGES 50000
#define E2 (2*NEDGES)
#define PAIRS (E2*NENV)          // 1,600,000
#define TILE_P 128               // pairs per CTA tile
#define NTILES (PAIRS/TILE_P)    // 12,500
#define NROWS (NENV*NNODES)      // 80,000
#define EDGE_GRID 444

// ---- scratch (no allocation allowed) ----
__device__ float g_nf[NROWS*NF];
__device__ float g_store[NROWS*EF];

__device__ __forceinline__ float tanh_fast(float x) {
    float y; asm("tanh.approx.f32 %0, %1;" : "=f"(y) : "f"(x)); return y;
}
__device__ __forceinline__ uint32_t pack_h2(float a, float b) {
    __half2 h = __floats2half2_rn(a, b);
    return *(uint32_t*)&h;
}
__device__ __forceinline__ void mma_f16(float* d, uint32_t a0, uint32_t a1,
                                        uint32_t a2, uint32_t a3,
                                        uint32_t b0, uint32_t b1) {
    asm volatile("mma.sync.aligned.m16n8k16.row.col.f32.f16.f16.f32 "
        "{%0,%1,%2,%3}, {%4,%5,%6,%7}, {%8,%9}, {%0,%1,%2,%3};"
        : "+f"(d[0]), "+f"(d[1]), "+f"(d[2]), "+f"(d[3])
        : "r"(a0), "r"(a1), "r"(a2), "r"(a3), "r"(b0), "r"(b1));
}

// ---- shared layout (32-bit words) ----
#define XSTRW 28                 // 24 used (48 halves, K padded 40->48)
#define HSTRW 36                 // 32 used (64 halves) / 32 floats for msg
#define OFF_W1F 0                        // 24 frags x 64 words
#define OFF_W2F (OFF_W1F + 24*64)        // 32 frags
#define OFF_W3F (OFF_W2F + 32*64)        // 16 frags
#define OFF_X   (OFF_W3F + 16*64)        // 128 x XSTRW
#define OFF_H   (OFF_X + 128*XSTRW)      // 128 x HSTRW
#define OFF_BASE (OFF_H + 128*HSTRW)     // 128 ints
#define OFF_B1  (OFF_BASE + 128)         // 64
#define OFF_B2  (OFF_B1 + 64)            // 64
#define OFF_B3  (OFF_B2 + 64)            // 32 (20 used)
#define SMEM_WORDS (OFF_B3 + 32)
#define SMEM_EDGE_BYTES (SMEM_WORDS * 4) // 52,352 B -> 3 CTAs/SM

__global__ void __launch_bounds__(128, 3)
edge_kernel(const float* __restrict__ nf,
            const int*   __restrict__ edges,
            const float* __restrict__ W1, const float* __restrict__ b1,
            const float* __restrict__ W2, const float* __restrict__ b2,
            const float* __restrict__ W3, const float* __restrict__ b3,
            float* __restrict__ store)
{
    extern __shared__ uint32_t sm[];
    uint32_t* wf1 = sm + OFF_W1F;
    uint32_t* wf2 = sm + OFF_W2F;
    uint32_t* wf3 = sm + OFF_W3F;
    const int tid  = threadIdx.x;
    const int wid  = tid >> 5;
    const int lane = tid & 31;
    uint32_t* sX = sm + OFF_X + wid * 32 * XSTRW;   // this warp's 32 pair rows (f16x2)
    uint32_t* sH = sm + OFF_H + wid * 32 * HSTRW;   // f16x2 for H, floats for msg
    int* sbase = (int*)(sm + OFF_BASE) + wid * 32;
    float* sb1 = (float*)(sm + OFF_B1);
    float* sb2 = (float*)(sm + OFF_B2);
    float* sb3 = (float*)(sm + OFF_B3);

    // ---- stage weights as f16 fragments (m16n8k16.col B layout), once per CTA ----
    // frag f, lane t, reg w: value = pack(W[n][k0], W[n][k0+1]),
    //   n = (f%NB)*8 + t/4 ; k0 = (f/NB)*16 + (t%4)*2 + w*8
    for (int s = tid; s < 24*64; s += 128) {            // W1: [64][40], K padded to 48, NB=8
        int f = s >> 6, rem = s & 63, t = rem >> 1, w = rem & 1;
        int n = (f & 7)*8 + (t >> 2);
        int k0 = (f >> 3)*16 + (t & 3)*2 + w*8;
        float va = (k0   < 40) ? W1[n*40 + k0]     : 0.0f;
        float vb = (k0+1 < 40) ? W1[n*40 + k0 + 1] : 0.0f;
        wf1[s] = pack_h2(va, vb);
    }
    for (int s = tid; s < 32*64; s += 128) {            // W2: [64][64], NB=8
        int f = s >> 6, rem = s & 63, t = rem >> 1, w = rem & 1;
        int n = (f & 7)*8 + (t >> 2);
        int k0 = (f >> 3)*16 + (t & 3)*2 + w*8;
        wf2[s] = pack_h2(W2[n*64 + k0], W2[n*64 + k0 + 1]);
    }
    for (int s = tid; s < 16*64; s += 128) {            // W3: [20][64] padded N->32, NB=4
        int f = s >> 6, rem = s & 63, t = rem >> 1, w = rem & 1;
        int n = (f & 3)*8 + (t >> 2);
        int k0 = (f >> 2)*16 + (t & 3)*2 + w*8;
        wf3[s] = (n < EF) ? pack_h2(W3[n*64 + k0], W3[n*64 + k0 + 1]) : 0u;
    }
    if (tid < 64) { sb1[tid] = b1[tid]; sb2[tid] = b2[tid]; }
    if (tid < 32) sb3[tid] = (tid < EF) ? b3[tid] : 0.0f;
    // zero X pad words (k 40..47) once; gather never touches them
    *(uint4*)(sX + lane * XSTRW + 20) = make_uint4(0,0,0,0);
    __syncthreads();

    const int rq = lane >> 2;   // row in m16 (rows rq, rq+8; +16 for m=1)
    const int cq = lane & 3;

    for (int t = blockIdx.x; t < NTILES; t += gridDim.x) {
        __syncwarp();
        // ---------- gather: lane p loads pair p's src+dst rows, f16-convert ----------
        {
            int pid = t * TILE_P + wid * 32 + lane;
            int env = pid & 15, e2 = pid >> 4;
            int s = edges[e2];
            int d = edges[(e2 + NEDGES) % E2];
            int srow = env * NNODES + s;
            int drow = env * NNODES + d;
            sbase[lane] = srow * EF;
            const float4* sp = (const float4*)(nf + srow * NF);
            const float4* dp = (const float4*)(nf + drow * NF);
            uint32_t* dst = sX + lane * XSTRW;
            #pragma unroll
            for (int j = 0; j < 5; j += 2) {            // j = 0,2,4 covers 20 floats
                float4 u = sp[j];
                float4 v = (j < 4) ? sp[j+1] : make_float4(0,0,0,0);
                *(uint2*)(dst + j*2)     = make_uint2(pack_h2(u.x,u.y), pack_h2(u.z,u.w));
                if (j < 4)
                    *(uint2*)(dst + j*2+2) = make_uint2(pack_h2(v.x,v.y), pack_h2(v.z,v.w));
            }
            #pragma unroll
            for (int j = 0; j < 5; j += 2) {
                float4 u = dp[j];
                float4 v = (j < 4) ? dp[j+1] : make_float4(0,0,0,0);
                *(uint2*)(dst + 10 + j*2)     = make_uint2(pack_h2(u.x,u.y), pack_h2(u.z,u.w));
                if (j < 4)
                    *(uint2*)(dst + 10 + j*2+2) = make_uint2(pack_h2(v.x,v.y), pack_h2(v.z,v.w));
            }
        }
        __syncwarp();

        // ---------- phase 1: H1 = tanh(X @ W1^T + b1), K=48 (padded), M=32 ----------
        {
            float acc[8][2][4];
            #pragma unroll
            for (int n = 0; n < 8; n++)
                #pragma unroll
                for (int m = 0; m < 2; m++)
                    acc[n][m][0] = acc[n][m][1] = acc[n][m][2] = acc[n][m][3] = 0.0f;
            #pragma unroll
            for (int kc = 0; kc < 3; kc++) {
                uint32_t a[2][4];
                #pragma unroll
                for (int m = 0; m < 2; m++) {
                    int r0 = rq + m*16;
                    a[m][0] = sX[r0*XSTRW + kc*8 + cq];
                    a[m][1] = sX[(r0+8)*XSTRW + kc*8 + cq];
                    a[m][2] = sX[r0*XSTRW + kc*8 + cq + 4];
                    a[m][3] = sX[(r0+8)*XSTRW + kc*8 + cq + 4];
                }
                #pragma unroll
                for (int n = 0; n < 8; n++) {
                    uint2 b = *(const uint2*)&wf1[(kc*8 + n)*64 + lane*2];
                    mma_f16(acc[n][0], a[0][0], a[0][1], a[0][2], a[0][3], b.x, b.y);
                    mma_f16(acc[n][1], a[1][0], a[1][1], a[1][2], a[1][3], b.x, b.y);
                }
            }
            #pragma unroll
            for (int n = 0; n < 8; n++) {
                int c0 = n*8 + 2*cq;                    // cols c0, c0+1 ; word n*4+cq
                float bx = sb1[c0], by = sb1[c0+1];
                #pragma unroll
                for (int m = 0; m < 2; m++) {
                    int r0 = rq + m*16;
                    sH[r0*HSTRW + n*4 + cq] =
                        pack_h2(tanh_fast(acc[n][m][0] + bx), tanh_fast(acc[n][m][1] + by));
                    sH[(r0+8)*HSTRW + n*4 + cq] =
                        pack_h2(tanh_fast(acc[n][m][2] + bx), tanh_fast(acc[n][m][3] + by));
                }
            }
        }
        __syncwarp();

        // ---------- phase 2: H2 = tanh(H1 @ W2^T + b2), K=64, in place ----------
        {
            float acc[8][2][4];
            #pragma unroll
            for (int n = 0; n < 8; n++)
                #pragma unroll
                for (int m = 0; m < 2; m++)
                    acc[n][m][0] = acc[n][m][1] = acc[n][m][2] = acc[n][m][3] = 0.0f;
            #pragma unroll
            for (int kc = 0; kc < 4; kc++) {
                uint32_t a[2][4];
                #pragma unroll
                for (int m = 0; m < 2; m++) {
                    int r0 = rq + m*16;
                    a[m][0] = sH[r0*HSTRW + kc*8 + cq];
                    a[m][1] = sH[(r0+8)*HSTRW + kc*8 + cq];
                    a[m][2] = sH[r0*HSTRW + kc*8 + cq + 4];
                    a[m][3] = sH[(r0+8)*HSTRW + kc*8 + cq + 4];
                }
                #pragma unroll
                for (int n = 0; n < 8; n++) {
                    uint2 b = *(const uint2*)&wf2[(kc*8 + n)*64 + lane*2];
                    mma_f16(acc[n][0], a[0][0], a[0][1], a[0][2], a[0][3], b.x, b.y);
                    mma_f16(acc[n][1], a[1][0], a[1][1], a[1][2], a[1][3], b.x, b.y);
                }
            }
            __syncwarp();   // all lanes done reading H1 before overwrite
            #pragma unroll
            for (int n = 0; n < 8; n++) {
                int c0 = n*8 + 2*cq;
                float bx = sb2[c0], by = sb2[c0+1];
                #pragma unroll
                for (int m = 0; m < 2; m++) {
                    int r0 = rq + m*16;
                    sH[r0*HSTRW + n*4 + cq] =
                        pack_h2(tanh_fast(acc[n][m][0] + bx), tanh_fast(acc[n][m][1] + by));
                    sH[(r0+8)*HSTRW + n*4 + cq] =
                        pack_h2(tanh_fast(acc[n][m][2] + bx), tanh_fast(acc[n][m][3] + by));
                }
            }
        }
        __syncwarp();

        // ---------- phase 3: msg = H2 @ W3^T + b3 (N=32 padded), K=64 ----------
        {
            float acc[4][2][4];
            #pragma unroll
            for (int n = 0; n < 4; n++)
                #pragma unroll
                for (int m = 0; m < 2; m++)
                    acc[n][m][0] = acc[n][m][1] = acc[n][m][2] = acc[n][m][3] = 0.0f;
            #pragma unroll
            for (int kc = 0; kc < 4; kc++) {
                uint32_t a[2][4];
                #pragma unroll
                for (int m = 0; m < 2; m++) {
                    int r0 = rq + m*16;
                    a[m][0] = sH[r0*HSTRW + kc*8 + cq];
                    a[m][1] = sH[(r0+8)*HSTRW + kc*8 + cq];
                    a[m][2] = sH[r0*HSTRW + kc*8 + cq + 4];
                    a[m][3] = sH[(r0+8)*HSTRW + kc*8 + cq + 4];
                }
                #pragma unroll
                for (int n = 0; n < 4; n++) {
                    uint2 b = *(const uint2*)&wf3[(kc*4 + n)*64 + lane*2];
                    mma_f16(acc[n][0], a[0][0], a[0][1], a[0][2], a[0][3], b.x, b.y);
                    mma_f16(acc[n][1], a[1][0], a[1][1], a[1][2], a[1][3], b.x, b.y);
                }
            }
            __syncwarp();   // all lanes done reading H2 before overwriting with msg floats
            float* sHf = (float*)sH;
            #pragma unroll
            for (int n = 0; n < 4; n++) {
                int c0 = n*8 + 2*cq;
                float bx = sb3[c0], by = sb3[c0+1];
                #pragma unroll
                for (int m = 0; m < 2; m++) {
                    int r0 = rq + m*16;
                    *(float2*)&sHf[r0*HSTRW + c0] =
                        make_float2(acc[n][m][0] + bx, acc[n][m][1] + by);
                    *(float2*)&sHf[(r0+8)*HSTRW + c0] =
                        make_float2(acc[n][m][2] + bx, acc[n][m][3] + by);
                }
            }
        }
        __syncwarp();

        // ---------- scatter-add: lane p scatters pair p (5 x red.f32x4) ----------
        {
            float* dst = store + sbase[lane];
            const float* src = (const float*)sH + lane * HSTRW;
            atomicAdd((float4*)(dst +  0), *(const float4*)(src +  0));
            atomicAdd((float4*)(dst +  4), *(const float4*)(src +  4));
            atomicAdd((float4*)(dst +  8), *(const float4*)(src +  8));
            atomicAdd((float4*)(dst + 12), *(const float4*)(src + 12));
            atomicAdd((float4*)(dst + 16), *(const float4*)(src + 16));
        }
    }
}

// ---------------- GRU: one thread per (env,node) row; zeroes store after read ----------------
__global__ void __launch_bounds__(256)
gru_kernel(const float* __restrict__ nf_in,
           float* __restrict__ store,
           const float* __restrict__ Wih, const float* __restrict__ Whh,
           const float* __restrict__ bih, const float* __restrict__ bhh,
           float* __restrict__ nf_out)
{
    __shared__ float sWih[60*20], sWhh[60*20], sbih[60], sbhh[60];
    const int tid = threadIdx.x;
    for (int i = tid; i < 1200; i += 256) { sWih[i] = Wih[i]; sWhh[i] = Whh[i]; }
    if (tid < 60) { sbih[tid] = bih[tid]; sbhh[tid] = bhh[tid]; }
    __syncthreads();

    int row = blockIdx.x * 256 + tid;
    if (row >= NROWS) return;

    float m[20], h[20], out[20];
    float4* mp = (float4*)(store + row*20);
    const float4* hp = (const float4*)(nf_in + row*20);
    #pragma unroll
    for (int i = 0; i < 5; i++) { ((float4*)m)[i] = mp[i]; ((float4*)h)[i] = hp[i]; }
    // restore zeros for next edge pass (keeps store==0 invariant across graph replays)
    float4 z4 = make_float4(0.f, 0.f, 0.f, 0.f);
    #pragma unroll
    for (int i = 0; i < 5; i++) mp[i] = z4;

    #pragma unroll 4
    for (int c = 0; c < 20; c++) {
        float ir = sbih[c],      hr = sbhh[c];
        float iz = sbih[20 + c], hz = sbhh[20 + c];
        float in_ = sbih[40 + c], hn = sbhh[40 + c];
        #pragma unroll
        for (int k = 0; k < 20; k++) {
            ir  += m[k] * sWih[c*20 + k];
            iz  += m[k] * sWih[(20 + c)*20 + k];
            in_ += m[k] * sWih[(40 + c)*20 + k];
            hr  += h[k] * sWhh[c*20 + k];
            hz  += h[k] * sWhh[(20 + c)*20 + k];
            hn  += h[k] * sWhh[(40 + c)*20 + k];
        }
        float rr = 1.f / (1.f + expf(-(ir + hr)));
        float z  = 1.f / (1.f + expf(-(iz + hz)));
        float n  = tanhf(in_ + rr * hn);
        out[c] = (1.f - z) * n + z * h[c];
    }
    #pragma unroll
    for (int i = 0; i < 5; i++) ((float4*)(nf_out + row*20))[i] = ((float4*)out)[i];
}

extern "C" void kernel_launch(void* const* d_in, const int* in_sizes, int n_in,
                              void* d_out, int out_size)
{
    const float* nf0   = (const float*)d_in[0];
    const int*   edges = (const int*)  d_in[1];
    const float* W1 = (const float*)d_in[2];
    const float* b1 = (const float*)d_in[3];
    const float* W2 = (const float*)d_in[4];
    const float* b2 = (const float*)d_in[5];
    const float* W3 = (const float*)d_in[6];
    const float* b3 = (const float*)d_in[7];
    const float* Wih = (const float*)d_in[8];
    const float* Whh = (const float*)d_in[9];
    const float* bih = (const float*)d_in[10];
    const float* bhh = (const float*)d_in[11];
    float* out = (float*)d_out;

    float *nfbuf, *stbuf;
    cudaGetSymbolAddress((void**)&nfbuf, g_nf);
    cudaGetSymbolAddress((void**)&stbuf, g_store);

    cudaFuncSetAttribute(edge_kernel,
                         cudaFuncAttributeMaxDynamicSharedMemorySize, SMEM_EDGE_BYTES);

    for (int it = 0; it < 3; it++) {
        const float* nf_in = (it == 0) ? nf0 : nfbuf;
        float* nf_out = (it == 2) ? out : nfbuf;

        edge_kernel<<<EDGE_GRID, 128, SMEM_EDGE_BYTES>>>(nf_in, edges,
                                                         W1, b1, W2, b2, W3, b3, stbuf);
        gru_kernel<<<(NROWS + 255)/256, 256>>>(nf_in, stbuf, Wih, Whh, bih, bhh, nf_out);
    }
}

// round 9
// speedup vs baseline: 6.0246x; 1.0834x over previous
#include <cuda_runtime.h>
#include <cuda_fp16.h>
#include <math.h>
#include <stdint.h>

#define NF 20
#define EF 20
#define NENV 16
#define NNODES 5000
#define NEDGES 50000
#define E2 (2*NEDGES)
#define PAIRS (E2*NENV)          // 1,600,000
#define TILE_P 64                // pairs per CTA tile (4 warps x 16)
#define NTILES (PAIRS/TILE_P)    // 25,000
#define NROWS (NENV*NNODES)      // 80,000
#define EDGE_GRID 740            // 5 CTAs/SM x 148

// ---- scratch (no allocation allowed) ----
__device__ float g_nf[NROWS*NF];
__device__ float g_store[NROWS*EF];

__device__ __forceinline__ float tanh_fast(float x) {
    float y; asm("tanh.approx.f32 %0, %1;" : "=f"(y) : "f"(x)); return y;
}
__device__ __forceinline__ uint32_t pack_h2(float a, float b) {
    __half2 h = __floats2half2_rn(a, b);
    return *(uint32_t*)&h;
}
__device__ __forceinline__ void mma_f16(float* d, uint32_t a0, uint32_t a1,
                                        uint32_t a2, uint32_t a3,
                                        uint32_t b0, uint32_t b1) {
    asm volatile("mma.sync.aligned.m16n8k16.row.col.f32.f16.f16.f32 "
        "{%0,%1,%2,%3}, {%4,%5,%6,%7}, {%8,%9}, {%0,%1,%2,%3};"
        : "+f"(d[0]), "+f"(d[1]), "+f"(d[2]), "+f"(d[3])
        : "r"(a0), "r"(a1), "r"(a2), "r"(a3), "r"(b0), "r"(b1));
}

// ---- shared layout (32-bit words) ----
// weight fragments stored PAIRED: block (kc, q) of 128 words holds n-tiles 2q, 2q+1:
//   word index = blk*128 + lane*4 + e*2 + w   (e = n&1)
#define XSTRW 28                 // 20 data words (40 halves) + 4 pad (zeros) + 4 slack
#define OFF_W1F 0                // 12 blocks (3 kc x 4 q) x 128 = 1536
#define OFF_W2F 1536             // 16 blocks x 128 = 2048
#define OFF_W3F 3584             // 8 blocks (4 kc x 2 q) x 128 = 1024
#define OFF_X   4608             // 4 warps x 16 rows x XSTRW = 1792
#define OFF_BASE 6400            // 64 ints
#define OFF_B1  6464             // 64
#define OFF_B2  6528             // 64
#define OFF_B3  6592             // 32 (20 used)
#define SMEM_WORDS 6624
#define SMEM_EDGE_BYTES (SMEM_WORDS * 4)   // 26,496 B -> 5 CTAs/SM

__global__ void __launch_bounds__(128, 5)
edge_kernel(const float* __restrict__ nf,
            const int*   __restrict__ edges,
            const float* __restrict__ W1, const float* __restrict__ b1,
            const float* __restrict__ W2, const float* __restrict__ b2,
            const float* __restrict__ W3, const float* __restrict__ b3,
            float* __restrict__ store)
{
    extern __shared__ uint32_t sm[];
    uint32_t* wf1 = sm + OFF_W1F;
    uint32_t* wf2 = sm + OFF_W2F;
    uint32_t* wf3 = sm + OFF_W3F;
    const int tid  = threadIdx.x;
    const int wid  = tid >> 5;
    const int lane = tid & 31;
    uint32_t* sX = sm + OFF_X + wid * 16 * XSTRW;   // this warp's 16 pair rows
    int* sbase = (int*)(sm + OFF_BASE) + wid * 16;
    float* sb1 = (float*)(sm + OFF_B1);
    float* sb2 = (float*)(sm + OFF_B2);
    float* sb3 = (float*)(sm + OFF_B3);

    // ---- stage weights as PAIRED f16 fragments (m16n8k16.col B layout) ----
    // decode s: blk = s>>7 ; rem = s&127 ; t = rem>>2 ; e = (rem>>1)&1 ; w = rem&1
    // ntile = q*2 + e ; out-row = ntile*8 + (t>>2) ; k0 = kc*16 + (t&3)*2 + w*8
    for (int s = tid; s < 1536; s += 128) {             // W1 [64][40], K pad->48: kc=blk>>2, q=blk&3
        int blk = s >> 7, rem = s & 127;
        int t = rem >> 2, e = (rem >> 1) & 1, w = rem & 1;
        int kc = blk >> 2, q = blk & 3;
        int row = (q*2 + e)*8 + (t >> 2);
        int k0 = kc*16 + (t & 3)*2 + w*8;
        float va = (k0   < 40) ? W1[row*40 + k0]     : 0.0f;
        float vb = (k0+1 < 40) ? W1[row*40 + k0 + 1] : 0.0f;
        wf1[s] = pack_h2(va, vb);
    }
    for (int s = tid; s < 2048; s += 128) {             // W2 [64][64]: kc=blk>>2, q=blk&3
        int blk = s >> 7, rem = s & 127;
        int t = rem >> 2, e = (rem >> 1) & 1, w = rem & 1;
        int kc = blk >> 2, q = blk & 3;
        int row = (q*2 + e)*8 + (t >> 2);
        int k0 = kc*16 + (t & 3)*2 + w*8;
        wf2[s] = pack_h2(W2[row*64 + k0], W2[row*64 + k0 + 1]);
    }
    for (int s = tid; s < 1024; s += 128) {             // W3 [20][64] pad N->32: kc=blk>>1, q=blk&1
        int blk = s >> 7, rem = s & 127;
        int t = rem >> 2, e = (rem >> 1) & 1, w = rem & 1;
        int kc = blk >> 1, q = blk & 1;
        int row = (q*2 + e)*8 + (t >> 2);
        int k0 = kc*16 + (t & 3)*2 + w*8;
        wf3[s] = (row < EF) ? pack_h2(W3[row*64 + k0], W3[row*64 + k0 + 1]) : 0u;
    }
    if (tid < 64) { sb1[tid] = b1[tid]; sb2[tid] = b2[tid]; }
    if (tid < 32) sb3[tid] = (tid < EF) ? b3[tid] : 0.0f;
    // zero X pad words 20..23 (cols 40..47) once; gather/msg never touch them
    if (lane < 16) *(uint4*)(sX + lane * XSTRW + 20) = make_uint4(0,0,0,0);
    __syncthreads();

    const int rq = lane >> 2;   // row in m16 (rows rq, rq+8)
    const int cq = lane & 3;

    for (int t = blockIdx.x; t < NTILES; t += gridDim.x) {
        __syncwarp();   // prior scatter reads done before overwriting sX
        // ---------- gather: 2 lanes per pair; write 20 halves (10 words) each ----------
        {
            int p = lane >> 1, half = lane & 1;
            int pid = t * TILE_P + wid * 16 + p;
            int env = pid & 15, e2 = pid >> 4;
            int node = half ? edges[(e2 + NEDGES) % E2] : edges[e2];
            int grow = env * NNODES + node;
            if (!half) sbase[p] = grow * EF;
            const float4* gp = (const float4*)(nf + grow * NF);
            float4 v0 = gp[0], v1 = gp[1], v2 = gp[2], v3 = gp[3], v4 = gp[4];
            uint32_t* dst = sX + p * XSTRW + half * 10;
            *(uint2*)(dst + 0) = make_uint2(pack_h2(v0.x,v0.y), pack_h2(v0.z,v0.w));
            *(uint2*)(dst + 2) = make_uint2(pack_h2(v1.x,v1.y), pack_h2(v1.z,v1.w));
            *(uint2*)(dst + 4) = make_uint2(pack_h2(v2.x,v2.y), pack_h2(v2.z,v2.w));
            *(uint2*)(dst + 6) = make_uint2(pack_h2(v3.x,v3.y), pack_h2(v3.z,v3.w));
            *(uint2*)(dst + 8) = make_uint2(pack_h2(v4.x,v4.y), pack_h2(v4.z,v4.w));
        }
        __syncwarp();

        // ---------- phase 1: acc1 = X @ W1^T  (K=48 padded) ----------
        float acc1[8][4];
        #pragma unroll
        for (int n = 0; n < 8; n++)
            acc1[n][0] = acc1[n][1] = acc1[n][2] = acc1[n][3] = 0.0f;
        #pragma unroll
        for (int kc = 0; kc < 3; kc++) {
            uint32_t a0 = sX[rq*XSTRW + kc*8 + cq];
            uint32_t a1 = sX[(rq+8)*XSTRW + kc*8 + cq];
            uint32_t a2 = sX[rq*XSTRW + kc*8 + cq + 4];
            uint32_t a3 = sX[(rq+8)*XSTRW + kc*8 + cq + 4];
            #pragma unroll
            for (int q = 0; q < 4; q++) {
                uint4 b = *(const uint4*)&wf1[(kc*4 + q)*128 + lane*4];
                mma_f16(acc1[2*q],   a0, a1, a2, a3, b.x, b.y);
                mma_f16(acc1[2*q+1], a0, a1, a2, a3, b.z, b.w);
            }
        }
        // epilogue 1: tanh+bias, repack C frags -> A frags (NO SMEM)
        uint32_t aH[4][4];
        #pragma unroll
        for (int kc = 0; kc < 4; kc++) {
            float bx0 = sb1[16*kc + 2*cq],     by0 = sb1[16*kc + 2*cq + 1];
            float bx1 = sb1[16*kc + 8 + 2*cq], by1 = sb1[16*kc + 8 + 2*cq + 1];
            aH[kc][0] = pack_h2(tanh_fast(acc1[2*kc][0] + bx0),   tanh_fast(acc1[2*kc][1] + by0));
            aH[kc][1] = pack_h2(tanh_fast(acc1[2*kc][2] + bx0),   tanh_fast(acc1[2*kc][3] + by0));
            aH[kc][2] = pack_h2(tanh_fast(acc1[2*kc+1][0] + bx1), tanh_fast(acc1[2*kc+1][1] + by1));
            aH[kc][3] = pack_h2(tanh_fast(acc1[2*kc+1][2] + bx1), tanh_fast(acc1[2*kc+1][3] + by1));
        }

        // ---------- phase 2: acc2 = H1 @ W2^T (K=64), A in registers ----------
        float acc2[8][4];
        #pragma unroll
        for (int n = 0; n < 8; n++)
            acc2[n][0] = acc2[n][1] = acc2[n][2] = acc2[n][3] = 0.0f;
        #pragma unroll
        for (int kc = 0; kc < 4; kc++) {
            #pragma unroll
            for (int q = 0; q < 4; q++) {
                uint4 b = *(const uint4*)&wf2[(kc*4 + q)*128 + lane*4];
                mma_f16(acc2[2*q],   aH[kc][0], aH[kc][1], aH[kc][2], aH[kc][3], b.x, b.y);
                mma_f16(acc2[2*q+1], aH[kc][0], aH[kc][1], aH[kc][2], aH[kc][3], b.z, b.w);
            }
        }
        // epilogue 2: tanh+bias, repack -> A frags
        uint32_t aG[4][4];
        #pragma unroll
        for (int kc = 0; kc < 4; kc++) {
            float bx0 = sb2[16*kc + 2*cq],     by0 = sb2[16*kc + 2*cq + 1];
            float bx1 = sb2[16*kc + 8 + 2*cq], by1 = sb2[16*kc + 8 + 2*cq + 1];
            aG[kc][0] = pack_h2(tanh_fast(acc2[2*kc][0] + bx0),   tanh_fast(acc2[2*kc][1] + by0));
            aG[kc][1] = pack_h2(tanh_fast(acc2[2*kc][2] + bx0),   tanh_fast(acc2[2*kc][3] + by0));
            aG[kc][2] = pack_h2(tanh_fast(acc2[2*kc+1][0] + bx1), tanh_fast(acc2[2*kc+1][1] + by1));
            aG[kc][3] = pack_h2(tanh_fast(acc2[2*kc+1][2] + bx1), tanh_fast(acc2[2*kc+1][3] + by1));
        }

        // ---------- phase 3: acc3 = H2 @ W3^T (N=32 padded, K=64) ----------
        float acc3[4][4];
        #pragma unroll
        for (int n = 0; n < 4; n++)
            acc3[n][0] = acc3[n][1] = acc3[n][2] = acc3[n][3] = 0.0f;
        #pragma unroll
        for (int kc = 0; kc < 4; kc++) {
            #pragma unroll
            for (int q = 0; q < 2; q++) {
                uint4 b = *(const uint4*)&wf3[(kc*2 + q)*128 + lane*4];
                mma_f16(acc3[2*q],   aG[kc][0], aG[kc][1], aG[kc][2], aG[kc][3], b.x, b.y);
                mma_f16(acc3[2*q+1], aG[kc][0], aG[kc][1], aG[kc][2], aG[kc][3], b.z, b.w);
            }
        }
        // epilogue 3: msg floats overwrite dead X data (cols 0..19 only; pad words stay 0)
        {
            float* sXf = (float*)sX;
            #pragma unroll
            for (int n = 0; n < 2; n++) {       // cols 0..15
                int c0 = 8*n + 2*cq;
                float bx = sb3[c0], by = sb3[c0+1];
                *(float2*)&sXf[rq*XSTRW + c0]     = make_float2(acc3[n][0] + bx, acc3[n][1] + by);
                *(float2*)&sXf[(rq+8)*XSTRW + c0] = make_float2(acc3[n][2] + bx, acc3[n][3] + by);
            }
            if (cq < 2) {                       // n=2, cols 16..19 only
                int c0 = 16 + 2*cq;
                float bx = sb3[c0], by = sb3[c0+1];
                *(float2*)&sXf[rq*XSTRW + c0]     = make_float2(acc3[2][0] + bx, acc3[2][1] + by);
                *(float2*)&sXf[(rq+8)*XSTRW + c0] = make_float2(acc3[2][2] + bx, acc3[2][3] + by);
            }
            // n=3 (cols 24..31) unused — skipped
        }
        __syncwarp();

        // ---------- scatter-add: 2 lanes per pair ----------
        {
            int p = lane >> 1, half = lane & 1;
            float* dst = store + sbase[p];
            const float* src = (const float*)sX + p * XSTRW;
            if (!half) {
                atomicAdd((float4*)(dst + 0), *(const float4*)(src + 0));
                atomicAdd((float4*)(dst + 4), *(const float4*)(src + 4));
                atomicAdd((float4*)(dst + 8), *(const float4*)(src + 8));
            } else {
                atomicAdd((float4*)(dst + 12), *(const float4*)(src + 12));
                atomicAdd((float4*)(dst + 16), *(const float4*)(src + 16));
            }
        }
    }
}

// ---------------- GRU: one thread per (env,node) row; zeroes store after read ----------------
__global__ void __launch_bounds__(256)
gru_kernel(const float* __restrict__ nf_in,
           float* __restrict__ store,
           const float* __restrict__ Wih, const float* __restrict__ Whh,
           const float* __restrict__ bih, const float* __restrict__ bhh,
           float* __restrict__ nf_out)
{
    __shared__ float sWih[60*20], sWhh[60*20], sbih[60], sbhh[60];
    const int tid = threadIdx.x;
    for (int i = tid; i < 1200; i += 256) { sWih[i] = Wih[i]; sWhh[i] = Whh[i]; }
    if (tid < 60) { sbih[tid] = bih[tid]; sbhh[tid] = bhh[tid]; }
    __syncthreads();

    int row = blockIdx.x * 256 + tid;
    if (row >= NROWS) return;

    float m[20], h[20], out[20];
    float4* mp = (float4*)(store + row*20);
    const float4* hp = (const float4*)(nf_in + row*20);
    #pragma unroll
    for (int i = 0; i < 5; i++) { ((float4*)m)[i] = mp[i]; ((float4*)h)[i] = hp[i]; }
    // restore zeros for next edge pass (keeps store==0 invariant across graph replays)
    float4 z4 = make_float4(0.f, 0.f, 0.f, 0.f);
    #pragma unroll
    for (int i = 0; i < 5; i++) mp[i] = z4;

    #pragma unroll 2
    for (int c = 0; c < 20; c++) {
        float ir = sbih[c],      hr = sbhh[c];
        float iz = sbih[20 + c], hz = sbhh[20 + c];
        float in_ = sbih[40 + c], hn = sbhh[40 + c];
        #pragma unroll
        for (int j = 0; j < 5; j++) {
            float4 w;
            w = *(const float4*)&sWih[c*20 + 4*j];
            ir  += m[4*j]*w.x + m[4*j+1]*w.y + m[4*j+2]*w.z + m[4*j+3]*w.w;
            w = *(const float4*)&sWih[(20 + c)*20 + 4*j];
            iz  += m[4*j]*w.x + m[4*j+1]*w.y + m[4*j+2]*w.z + m[4*j+3]*w.w;
            w = *(const float4*)&sWih[(40 + c)*20 + 4*j];
            in_ += m[4*j]*w.x + m[4*j+1]*w.y + m[4*j+2]*w.z + m[4*j+3]*w.w;
            w = *(const float4*)&sWhh[c*20 + 4*j];
            hr  += h[4*j]*w.x + h[4*j+1]*w.y + h[4*j+2]*w.z + h[4*j+3]*w.w;
            w = *(const float4*)&sWhh[(20 + c)*20 + 4*j];
            hz  += h[4*j]*w.x + h[4*j+1]*w.y + h[4*j+2]*w.z + h[4*j+3]*w.w;
            w = *(const float4*)&sWhh[(40 + c)*20 + 4*j];
            hn  += h[4*j]*w.x + h[4*j+1]*w.y + h[4*j+2]*w.z + h[4*j+3]*w.w;
        }
        float rr = 1.f / (1.f + expf(-(ir + hr)));
        float z  = 1.f / (1.f + expf(-(iz + hz)));
        float n  = tanhf(in_ + rr * hn);
        out[c] = (1.f - z) * n + z * h[c];
    }
    #pragma unroll
    for (int i = 0; i < 5; i++) ((float4*)(nf_out + row*20))[i] = ((float4*)out)[i];
}

extern "C" void kernel_launch(void* const* d_in, const int* in_sizes, int n_in,
                              void* d_out, int out_size)
{
    const float* nf0   = (const float*)d_in[0];
    const int*   edges = (const int*)  d_in[1];
    const float* W1 = (const float*)d_in[2];
    const float* b1 = (const float*)d_in[3];
    const float* W2 = (const float*)d_in[4];
    const float* b2 = (const float*)d_in[5];
    const float* W3 = (const float*)d_in[6];
    const float* b3 = (const float*)d_in[7];
    const float* Wih = (const float*)d_in[8];
    const float* Whh = (const float*)d_in[9];
    const float* bih = (const float*)d_in[10];
    const float* bhh = (const float*)d_in[11];
    float* out = (float*)d_out;

    float *nfbuf, *stbuf;
    cudaGetSymbolAddress((void**)&nfbuf, g_nf);
    cudaGetSymbolAddress((void**)&stbuf, g_store);

    cudaFuncSetAttribute(edge_kernel,
                         cudaFuncAttributeMaxDynamicSharedMemorySize, SMEM_EDGE_BYTES);

    for (int it = 0; it < 3; it++) {
        const float* nf_in = (it == 0) ? nf0 : nfbuf;
        float* nf_out = (it == 2) ? out : nfbuf;

        edge_kernel<<<EDGE_GRID, 128, SMEM_EDGE_BYTES>>>(nf_in, edges,
                                                         W1, b1, W2, b2, W3, b3, stbuf);
        gru_kernel<<<(NROWS + 255)/256, 256>>>(nf_in, stbuf, Wih, Whh, bih, bhh, nf_out);
    }
}

// round 10
// speedup vs baseline: 6.1365x; 1.0186x over previous
#include <cuda_runtime.h>
#include <cuda_fp16.h>
#include <math.h>
#include <stdint.h>

#define NF 20
#define EF 20
#define NENV 16
#define NNODES 5000
#define NEDGES 50000
#define E2 (2*NEDGES)
#define PAIRS (E2*NENV)          // 1,600,000
#define TILE_P 64                // pairs per CTA tile (4 warps x 16)
#define NTILES (PAIRS/TILE_P)    // 25,000
#define NROWS (NENV*NNODES)      // 80,000
#define EDGE_GRID 592            // 4 CTAs/SM x 148

// ---- scratch (no allocation allowed) ----
__device__ float g_nf[NROWS*NF];
__device__ float g_store[NROWS*EF];

__device__ __forceinline__ float tanh_fast(float x) {
    float y; asm("tanh.approx.f32 %0, %1;" : "=f"(y) : "f"(x)); return y;
}
__device__ __forceinline__ float sigmoid_fast(float x) {
    return 0.5f * tanh_fast(0.5f * x) + 0.5f;
}
__device__ __forceinline__ uint32_t pack_h2(float a, float b) {
    __half2 h = __floats2half2_rn(a, b);
    return *(uint32_t*)&h;
}
__device__ __forceinline__ void mma_f16(float* d, uint32_t a0, uint32_t a1,
                                        uint32_t a2, uint32_t a3,
                                        uint32_t b0, uint32_t b1) {
    asm volatile("mma.sync.aligned.m16n8k16.row.col.f32.f16.f16.f32 "
        "{%0,%1,%2,%3}, {%4,%5,%6,%7}, {%8,%9}, {%0,%1,%2,%3};"
        : "+f"(d[0]), "+f"(d[1]), "+f"(d[2]), "+f"(d[3])
        : "r"(a0), "r"(a1), "r"(a2), "r"(a3), "r"(b0), "r"(b1));
}

// ---- shared layout (32-bit words) ----
// weight fragments PAIRED: block (kc,q) of 128 words holds n-tiles 2q,2q+1:
//   word = blk*128 + lane*4 + e*2 + w
#define XSTRW 28                 // 20 data words + 4 zero-pad + 4 slack
#define OFF_W1F 0                // 12 blocks x 128 = 1536
#define OFF_W2F 1536             // 16 blocks x 128 = 2048
#define OFF_W3F 3584             // 8 blocks x 128 = 1024
#define OFF_X   4608             // 4 warps x 16 x XSTRW = 1792
#define OFF_BASE 6400            // 64 ints
#define OFF_B1  6464
#define OFF_B2  6528
#define OFF_B3  6592
#define SMEM_WORDS 6624
#define SMEM_EDGE_BYTES (SMEM_WORDS * 4)   // 26,496 B

__global__ void __launch_bounds__(128, 4)
edge_kernel(const float* __restrict__ nf,
            const int*   __restrict__ edges,
            const float* __restrict__ W1, const float* __restrict__ b1,
            const float* __restrict__ W2, const float* __restrict__ b2,
            const float* __restrict__ W3, const float* __restrict__ b3,
            float* __restrict__ store)
{
    extern __shared__ uint32_t sm[];
    uint32_t* wf1 = sm + OFF_W1F;
    uint32_t* wf2 = sm + OFF_W2F;
    uint32_t* wf3 = sm + OFF_W3F;
    const int tid  = threadIdx.x;
    const int wid  = tid >> 5;
    const int lane = tid & 31;
    uint32_t* sX = sm + OFF_X + wid * 16 * XSTRW;
    int* sbase = (int*)(sm + OFF_BASE) + wid * 16;
    float* sb1 = (float*)(sm + OFF_B1);
    float* sb2 = (float*)(sm + OFF_B2);
    float* sb3 = (float*)(sm + OFF_B3);

    // ---- stage weights as PAIRED f16 fragments (m16n8k16.col B layout) ----
    for (int s = tid; s < 1536; s += 128) {             // W1 [64][40], K pad->48
        int blk = s >> 7, rem = s & 127;
        int t = rem >> 2, e = (rem >> 1) & 1, w = rem & 1;
        int kc = blk >> 2, q = blk & 3;
        int row = (q*2 + e)*8 + (t >> 2);
        int k0 = kc*16 + (t & 3)*2 + w*8;
        float va = (k0   < 40) ? W1[row*40 + k0]     : 0.0f;
        float vb = (k0+1 < 40) ? W1[row*40 + k0 + 1] : 0.0f;
        wf1[s] = pack_h2(va, vb);
    }
    for (int s = tid; s < 2048; s += 128) {             // W2 [64][64]
        int blk = s >> 7, rem = s & 127;
        int t = rem >> 2, e = (rem >> 1) & 1, w = rem & 1;
        int kc = blk >> 2, q = blk & 3;
        int row = (q*2 + e)*8 + (t >> 2);
        int k0 = kc*16 + (t & 3)*2 + w*8;
        wf2[s] = pack_h2(W2[row*64 + k0], W2[row*64 + k0 + 1]);
    }
    for (int s = tid; s < 1024; s += 128) {             // W3 [20][64] pad N->32
        int blk = s >> 7, rem = s & 127;
        int t = rem >> 2, e = (rem >> 1) & 1, w = rem & 1;
        int kc = blk >> 1, q = blk & 1;
        int row = (q*2 + e)*8 + (t >> 2);
        int k0 = kc*16 + (t & 3)*2 + w*8;
        wf3[s] = (row < EF) ? pack_h2(W3[row*64 + k0], W3[row*64 + k0 + 1]) : 0u;
    }
    if (tid < 64) { sb1[tid] = b1[tid]; sb2[tid] = b2[tid]; }
    if (tid < 32) sb3[tid] = (tid < EF) ? b3[tid] : 0.0f;
    if (lane < 16) *(uint4*)(sX + lane * XSTRW + 20) = make_uint4(0,0,0,0);
    __syncthreads();

    const int rq = lane >> 2;
    const int cq = lane & 3;
    const int p    = lane >> 1;   // pair row this lane gathers/scatters
    const int half = lane & 1;

    // ---- prologue prefetch: tile blockIdx.x ----
    uint2 pf0, pf1, pf2, pf3, pf4;
    int pfb;
    {
        int pid = blockIdx.x * TILE_P + wid * 16 + p;
        int env = pid & 15, e2 = pid >> 4;
        int node = half ? edges[(e2 + NEDGES) % E2] : edges[e2];
        int grow = env * NNODES + node;
        pfb = grow * EF;
        const float4* gp = (const float4*)(nf + grow * NF);
        float4 v0 = gp[0], v1 = gp[1], v2 = gp[2], v3 = gp[3], v4 = gp[4];
        pf0 = make_uint2(pack_h2(v0.x,v0.y), pack_h2(v0.z,v0.w));
        pf1 = make_uint2(pack_h2(v1.x,v1.y), pack_h2(v1.z,v1.w));
        pf2 = make_uint2(pack_h2(v2.x,v2.y), pack_h2(v2.z,v2.w));
        pf3 = make_uint2(pack_h2(v3.x,v3.y), pack_h2(v3.z,v3.w));
        pf4 = make_uint2(pack_h2(v4.x,v4.y), pack_h2(v4.z,v4.w));
    }

    for (int t = blockIdx.x; t < NTILES; t += gridDim.x) {
        __syncwarp();   // prior scatter issued before overwriting sX
        // ---------- store prefetched X ----------
        {
            uint32_t* dst = sX + p * XSTRW + half * 10;
            *(uint2*)(dst + 0) = pf0;
            *(uint2*)(dst + 2) = pf1;
            *(uint2*)(dst + 4) = pf2;
            *(uint2*)(dst + 6) = pf3;
            *(uint2*)(dst + 8) = pf4;
            if (!half) sbase[p] = pfb;
        }
        __syncwarp();

        // ---------- load ALL phase-1 A fragments up front ----------
        uint32_t a1p[3][4];
        #pragma unroll
        for (int kc = 0; kc < 3; kc++) {
            a1p[kc][0] = sX[rq*XSTRW + kc*8 + cq];
            a1p[kc][1] = sX[(rq+8)*XSTRW + kc*8 + cq];
            a1p[kc][2] = sX[rq*XSTRW + kc*8 + cq + 4];
            a1p[kc][3] = sX[(rq+8)*XSTRW + kc*8 + cq + 4];
        }

        // ---------- prefetch NEXT tile (LDGs fly under the MMA phases) ----------
        {
            int tn = t + gridDim.x;
            if (tn >= NTILES) tn = t;      // harmless re-load on last tile
            int pid = tn * TILE_P + wid * 16 + p;
            int env = pid & 15, e2 = pid >> 4;
            int node = half ? edges[(e2 + NEDGES) % E2] : edges[e2];
            int grow = env * NNODES + node;
            pfb = grow * EF;
            const float4* gp = (const float4*)(nf + grow * NF);
            float4 v0 = gp[0], v1 = gp[1], v2 = gp[2], v3 = gp[3], v4 = gp[4];
            pf0 = make_uint2(pack_h2(v0.x,v0.y), pack_h2(v0.z,v0.w));
            pf1 = make_uint2(pack_h2(v1.x,v1.y), pack_h2(v1.z,v1.w));
            pf2 = make_uint2(pack_h2(v2.x,v2.y), pack_h2(v2.z,v2.w));
            pf3 = make_uint2(pack_h2(v3.x,v3.y), pack_h2(v3.z,v3.w));
            pf4 = make_uint2(pack_h2(v4.x,v4.y), pack_h2(v4.z,v4.w));
        }

        // ---------- phase 1: acc1 = X @ W1^T (K=48 padded) ----------
        float acc1[8][4];
        #pragma unroll
        for (int n = 0; n < 8; n++)
            acc1[n][0] = acc1[n][1] = acc1[n][2] = acc1[n][3] = 0.0f;
        #pragma unroll
        for (int kc = 0; kc < 3; kc++) {
            #pragma unroll
            for (int q = 0; q < 4; q++) {
                uint4 b = *(const uint4*)&wf1[(kc*4 + q)*128 + lane*4];
                mma_f16(acc1[2*q],   a1p[kc][0], a1p[kc][1], a1p[kc][2], a1p[kc][3], b.x, b.y);
                mma_f16(acc1[2*q+1], a1p[kc][0], a1p[kc][1], a1p[kc][2], a1p[kc][3], b.z, b.w);
            }
        }
        // epilogue 1: tanh+bias, C frags -> A frags (no SMEM)
        uint32_t aH[4][4];
        #pragma unroll
        for (int kc = 0; kc < 4; kc++) {
            float bx0 = sb1[16*kc + 2*cq],     by0 = sb1[16*kc + 2*cq + 1];
            float bx1 = sb1[16*kc + 8 + 2*cq], by1 = sb1[16*kc + 8 + 2*cq + 1];
            aH[kc][0] = pack_h2(tanh_fast(acc1[2*kc][0] + bx0),   tanh_fast(acc1[2*kc][1] + by0));
            aH[kc][1] = pack_h2(tanh_fast(acc1[2*kc][2] + bx0),   tanh_fast(acc1[2*kc][3] + by0));
            aH[kc][2] = pack_h2(tanh_fast(acc1[2*kc+1][0] + bx1), tanh_fast(acc1[2*kc+1][1] + by1));
            aH[kc][3] = pack_h2(tanh_fast(acc1[2*kc+1][2] + bx1), tanh_fast(acc1[2*kc+1][3] + by1));
        }

        // ---------- phase 2: acc2 = H1 @ W2^T (K=64) ----------
        float acc2[8][4];
        #pragma unroll
        for (int n = 0; n < 8; n++)
            acc2[n][0] = acc2[n][1] = acc2[n][2] = acc2[n][3] = 0.0f;
        #pragma unroll
        for (int kc = 0; kc < 4; kc++) {
            #pragma unroll
            for (int q = 0; q < 4; q++) {
                uint4 b = *(const uint4*)&wf2[(kc*4 + q)*128 + lane*4];
                mma_f16(acc2[2*q],   aH[kc][0], aH[kc][1], aH[kc][2], aH[kc][3], b.x, b.y);
                mma_f16(acc2[2*q+1], aH[kc][0], aH[kc][1], aH[kc][2], aH[kc][3], b.z, b.w);
            }
        }
        // epilogue 2
        uint32_t aG[4][4];
        #pragma unroll
        for (int kc = 0; kc < 4; kc++) {
            float bx0 = sb2[16*kc + 2*cq],     by0 = sb2[16*kc + 2*cq + 1];
            float bx1 = sb2[16*kc + 8 + 2*cq], by1 = sb2[16*kc + 8 + 2*cq + 1];
            aG[kc][0] = pack_h2(tanh_fast(acc2[2*kc][0] + bx0),   tanh_fast(acc2[2*kc][1] + by0));
            aG[kc][1] = pack_h2(tanh_fast(acc2[2*kc][2] + bx0),   tanh_fast(acc2[2*kc][3] + by0));
            aG[kc][2] = pack_h2(tanh_fast(acc2[2*kc+1][0] + bx1), tanh_fast(acc2[2*kc+1][1] + by1));
            aG[kc][3] = pack_h2(tanh_fast(acc2[2*kc+1][2] + bx1), tanh_fast(acc2[2*kc+1][3] + by1));
        }

        // ---------- phase 3: acc3 = H2 @ W3^T (N=32 padded, K=64) ----------
        float acc3[4][4];
        #pragma unroll
        for (int n = 0; n < 4; n++)
            acc3[n][0] = acc3[n][1] = acc3[n][2] = acc3[n][3] = 0.0f;
        #pragma unroll
        for (int kc = 0; kc < 4; kc++) {
            #pragma unroll
            for (int q = 0; q < 2; q++) {
                uint4 b = *(const uint4*)&wf3[(kc*2 + q)*128 + lane*4];
                mma_f16(acc3[2*q],   aG[kc][0], aG[kc][1], aG[kc][2], aG[kc][3], b.x, b.y);
                mma_f16(acc3[2*q+1], aG[kc][0], aG[kc][1], aG[kc][2], aG[kc][3], b.z, b.w);
            }
        }
        // epilogue 3: msg floats overwrite dead X cols 0..19 (pad words untouched)
        {
            float* sXf = (float*)sX;
            #pragma unroll
            for (int n = 0; n < 2; n++) {
                int c0 = 8*n + 2*cq;
                float bx = sb3[c0], by = sb3[c0+1];
                *(float2*)&sXf[rq*XSTRW + c0]     = make_float2(acc3[n][0] + bx, acc3[n][1] + by);
                *(float2*)&sXf[(rq+8)*XSTRW + c0] = make_float2(acc3[n][2] + bx, acc3[n][3] + by);
            }
            if (cq < 2) {
                int c0 = 16 + 2*cq;
                float bx = sb3[c0], by = sb3[c0+1];
                *(float2*)&sXf[rq*XSTRW + c0]     = make_float2(acc3[2][0] + bx, acc3[2][1] + by);
                *(float2*)&sXf[(rq+8)*XSTRW + c0] = make_float2(acc3[2][2] + bx, acc3[2][3] + by);
            }
        }
        __syncwarp();

        // ---------- scatter-add: 2 lanes per pair ----------
        {
            float* dst = store + sbase[p];
            const float* src = (const float*)sX + p * XSTRW;
            if (!half) {
                atomicAdd((float4*)(dst + 0), *(const float4*)(src + 0));
                atomicAdd((float4*)(dst + 4), *(const float4*)(src + 4));
                atomicAdd((float4*)(dst + 8), *(const float4*)(src + 8));
            } else {
                atomicAdd((float4*)(dst + 12), *(const float4*)(src + 12));
                atomicAdd((float4*)(dst + 16), *(const float4*)(src + 16));
            }
        }
    }
}

// ---------------- GRU: one thread per (env,node) row; zeroes store after read ----------------
__global__ void __launch_bounds__(256)
gru_kernel(const float* __restrict__ nf_in,
           float* __restrict__ store,
           const float* __restrict__ Wih, const float* __restrict__ Whh,
           const float* __restrict__ bih, const float* __restrict__ bhh,
           float* __restrict__ nf_out)
{
    __shared__ float sWih[60*20], sWhh[60*20], sbih[60], sbhh[60];
    const int tid = threadIdx.x;
    for (int i = tid; i < 1200; i += 256) { sWih[i] = Wih[i]; sWhh[i] = Whh[i]; }
    if (tid < 60) { sbih[tid] = bih[tid]; sbhh[tid] = bhh[tid]; }
    __syncthreads();

    int row = blockIdx.x * 256 + tid;
    if (row >= NROWS) return;

    float m[20], h[20], out[20];
    float4* mp = (float4*)(store + row*20);
    const float4* hp = (const float4*)(nf_in + row*20);
    #pragma unroll
    for (int i = 0; i < 5; i++) { ((float4*)m)[i] = mp[i]; ((float4*)h)[i] = hp[i]; }
    float4 z4 = make_float4(0.f, 0.f, 0.f, 0.f);
    #pragma unroll
    for (int i = 0; i < 5; i++) mp[i] = z4;   // keep store==0 invariant for replays

    #pragma unroll 2
    for (int c = 0; c < 20; c++) {
        float ir = sbih[c],      hr = sbhh[c];
        float iz = sbih[20 + c], hz = sbhh[20 + c];
        float in_ = sbih[40 + c], hn = sbhh[40 + c];
        #pragma unroll
        for (int j = 0; j < 5; j++) {
            float4 w;
            w = *(const float4*)&sWih[c*20 + 4*j];
            ir  += m[4*j]*w.x + m[4*j+1]*w.y + m[4*j+2]*w.z + m[4*j+3]*w.w;
            w = *(const float4*)&sWih[(20 + c)*20 + 4*j];
            iz  += m[4*j]*w.x + m[4*j+1]*w.y + m[4*j+2]*w.z + m[4*j+3]*w.w;
            w = *(const float4*)&sWih[(40 + c)*20 + 4*j];
            in_ += m[4*j]*w.x + m[4*j+1]*w.y + m[4*j+2]*w.z + m[4*j+3]*w.w;
            w = *(const float4*)&sWhh[c*20 + 4*j];
            hr  += h[4*j]*w.x + h[4*j+1]*w.y + h[4*j+2]*w.z + h[4*j+3]*w.w;
            w = *(const float4*)&sWhh[(20 + c)*20 + 4*j];
            hz  += h[4*j]*w.x + h[4*j+1]*w.y + h[4*j+2]*w.z + h[4*j+3]*w.w;
            w = *(const float4*)&sWhh[(40 + c)*20 + 4*j];
            hn  += h[4*j]*w.x + h[4*j+1]*w.y + h[4*j+2]*w.z + h[4*j+3]*w.w;
        }
        float rr = sigmoid_fast(ir + hr);
        float z  = sigmoid_fast(iz + hz);
        float n  = tanh_fast(in_ + rr * hn);
        out[c] = (1.f - z) * n + z * h[c];
    }
    #pragma unroll
    for (int i = 0; i < 5; i++) ((float4*)(nf_out + row*20))[i] = ((float4*)out)[i];
}

// no-op: shifts launch indices so ncu -s 5 captures the 3rd edge_kernel
__global__ void nop_kernel() {}

extern "C" void kernel_launch(void* const* d_in, const int* in_sizes, int n_in,
                              void* d_out, int out_size)
{
    const float* nf0   = (const float*)d_in[0];
    const int*   edges = (const int*)  d_in[1];
    const float* W1 = (const float*)d_in[2];
    const float* b1 = (const float*)d_in[3];
    const float* W2 = (const float*)d_in[4];
    const float* b2 = (const float*)d_in[5];
    const float* W3 = (const float*)d_in[6];
    const float* b3 = (const float*)d_in[7];
    const float* Wih = (const float*)d_in[8];
    const float* Whh = (const float*)d_in[9];
    const float* bih = (const float*)d_in[10];
    const float* bhh = (const float*)d_in[11];
    float* out = (float*)d_out;

    float *nfbuf, *stbuf;
    cudaGetSymbolAddress((void**)&nfbuf, g_nf);
    cudaGetSymbolAddress((void**)&stbuf, g_store);

    cudaFuncSetAttribute(edge_kernel,
                         cudaFuncAttributeMaxDynamicSharedMemorySize, SMEM_EDGE_BYTES);

    for (int it = 0; it < 3; it++) {
        const float* nf_in = (it == 0) ? nf0 : nfbuf;
        float* nf_out = (it == 2) ? out : nfbuf;

        if (it == 2) nop_kernel<<<1, 32>>>();   // launch #4 -> edge #3 is launch #5
        edge_kernel<<<EDGE_GRID, 128, SMEM_EDGE_BYTES>>>(nf_in, edges,
                                                         W1, b1, W2, b2, W3, b3, stbuf);
        gru_kernel<<<(NROWS + 255)/256, 256>>>(nf_in, stbuf, Wih, Whh, bih, bhh, nf_out);
    }
}